// round 1
// baseline (speedup 1.0000x reference)
#include <cuda_runtime.h>
#include <math.h>

#define D_MODEL   1024
#define N_EXPERTS 8
#define D_FF      4096
#define T_TOKENS  8192
#define TOP_K     2
#define TOTAL_SLOTS (T_TOKENS * TOP_K)

// Scratch (static __device__ — allocation-free per harness rules)
__device__ float g_H[(size_t)TOTAL_SLOTS * D_FF];   // 256 MB activations
__device__ int   g_slot_token[TOTAL_SLOTS];
__device__ float g_slot_w[TOTAL_SLOTS];
__device__ int   g_topk_idx[T_TOKENS * TOP_K];
__device__ float g_topk_w[T_TOKENS * TOP_K];
__device__ int   g_cnt[N_EXPERTS];
__device__ int   g_off[N_EXPERTS + 1];
__device__ int   g_cursor[N_EXPERTS];

__device__ __forceinline__ float gelu_exact(float h) {
    return 0.5f * h * (1.0f + erff(h * 0.70710678118654752440f));
}

__global__ void init_kernel() {
    int i = threadIdx.x;
    if (i < N_EXPERTS) g_cnt[i] = 0;
}

// One warp per token: logits, softmax, top-2, expert counting.
__global__ void gate_kernel(const float* __restrict__ x,
                            const float* __restrict__ Wg,
                            const float* __restrict__ bg,
                            float* __restrict__ gate_out)
{
    int warp = threadIdx.x >> 5;
    int lane = threadIdx.x & 31;
    int t = blockIdx.x * (blockDim.x >> 5) + warp;
    if (t >= T_TOKENS) return;

    float acc[N_EXPERTS];
#pragma unroll
    for (int e = 0; e < N_EXPERTS; e++) acc[e] = 0.0f;

    const float* xr = x + (size_t)t * D_MODEL;
    for (int d = lane; d < D_MODEL; d += 32) {
        float xv = xr[d];
        const float4 w0 = *(const float4*)(Wg + (size_t)d * N_EXPERTS);
        const float4 w1 = *(const float4*)(Wg + (size_t)d * N_EXPERTS + 4);
        acc[0] += xv * w0.x; acc[1] += xv * w0.y;
        acc[2] += xv * w0.z; acc[3] += xv * w0.w;
        acc[4] += xv * w1.x; acc[5] += xv * w1.y;
        acc[6] += xv * w1.z; acc[7] += xv * w1.w;
    }
#pragma unroll
    for (int e = 0; e < N_EXPERTS; e++) {
#pragma unroll
        for (int o = 16; o > 0; o >>= 1)
            acc[e] += __shfl_xor_sync(0xffffffffu, acc[e], o);
    }

    if (lane == 0) {
        float logit[N_EXPERTS];
        float mx = -1e30f;
#pragma unroll
        for (int e = 0; e < N_EXPERTS; e++) {
            logit[e] = acc[e] + bg[e];
            gate_out[(size_t)t * N_EXPERTS + e] = logit[e];
            mx = fmaxf(mx, logit[e]);
        }
        float p[N_EXPERTS];
        float sum = 0.0f;
#pragma unroll
        for (int e = 0; e < N_EXPERTS; e++) { p[e] = expf(logit[e] - mx); sum += p[e]; }
        float inv = 1.0f / sum;
#pragma unroll
        for (int e = 0; e < N_EXPERTS; e++) p[e] *= inv;

        // top-2, lowest-index tie-break (strict >)
        int i0 = 0; float v0 = p[0];
#pragma unroll
        for (int e = 1; e < N_EXPERTS; e++) if (p[e] > v0) { v0 = p[e]; i0 = e; }
        int i1 = -1; float v1 = -1e30f;
#pragma unroll
        for (int e = 0; e < N_EXPERTS; e++) {
            if (e == i0) continue;
            if (p[e] > v1) { v1 = p[e]; i1 = e; }
        }
        g_topk_idx[t * 2 + 0] = i0; g_topk_w[t * 2 + 0] = v0;
        g_topk_idx[t * 2 + 1] = i1; g_topk_w[t * 2 + 1] = v1;
        atomicAdd(&g_cnt[i0], 1);
        atomicAdd(&g_cnt[i1], 1);
    }
}

__global__ void prefix_kernel() {
    if (threadIdx.x == 0) {
        int s = 0;
        for (int e = 0; e < N_EXPERTS; e++) {
            g_off[e] = s;
            g_cursor[e] = s;
            s += g_cnt[e];
        }
        g_off[N_EXPERTS] = s;
    }
}

__global__ void scatter_kernel() {
    int t = blockIdx.x * blockDim.x + threadIdx.x;
    if (t >= T_TOKENS) return;
#pragma unroll
    for (int k = 0; k < TOP_K; k++) {
        int e = g_topk_idx[t * 2 + k];
        int pos = atomicAdd(&g_cursor[e], 1);
        g_slot_token[pos] = t;
        g_slot_w[pos] = g_topk_w[t * 2 + k];
    }
}

// GEMM1: H[slot, f] = gelu( x[token[slot]] @ W1[e] + b1[e] )
// 64x64 tile, BK=16, 256 threads, 4x4 register tile.
__global__ __launch_bounds__(256) void ffn1_kernel(const float* __restrict__ x,
                                                   const float* __restrict__ W1,
                                                   const float* __restrict__ b1)
{
    int e = blockIdx.z;
    int mBase = g_off[e] + blockIdx.x * 64;
    int mEnd  = g_off[e + 1];
    if (mBase >= mEnd) return;
    int n0 = blockIdx.y * 64;

    __shared__ float As[16][64];
    __shared__ float Bs[16][64];
    __shared__ int   stok[64];

    int tid = threadIdx.x;
    if (tid < 64) {
        int m = mBase + tid;
        stok[tid] = (m < mEnd) ? g_slot_token[m] : -1;
    }
    __syncthreads();

    int ty = tid >> 4, tx = tid & 15;
    int ar = tid >> 2;           // A row within tile (0..63)
    int ac = (tid & 3) * 4;      // A col group (0..12)
    int br = tid >> 4;           // B k-row (0..15)
    int bc = (tid & 15) * 4;     // B col (0..60)

    int tokA = stok[ar];
    const float* W1e = W1 + (size_t)e * D_MODEL * D_FF;

    float acc[4][4];
#pragma unroll
    for (int i = 0; i < 4; i++)
#pragma unroll
        for (int j = 0; j < 4; j++) acc[i][j] = 0.0f;

    for (int k0 = 0; k0 < D_MODEL; k0 += 16) {
        float4 av = make_float4(0.f, 0.f, 0.f, 0.f);
        if (tokA >= 0)
            av = *(const float4*)(x + (size_t)tokA * D_MODEL + k0 + ac);
        As[ac + 0][ar] = av.x; As[ac + 1][ar] = av.y;
        As[ac + 2][ar] = av.z; As[ac + 3][ar] = av.w;

        float4 bv = *(const float4*)(W1e + (size_t)(k0 + br) * D_FF + n0 + bc);
        *(float4*)&Bs[br][bc] = bv;
        __syncthreads();

#pragma unroll
        for (int kk = 0; kk < 16; kk++) {
            float4 a = *(float4*)&As[kk][ty * 4];
            float4 b = *(float4*)&Bs[kk][tx * 4];
            acc[0][0] += a.x * b.x; acc[0][1] += a.x * b.y; acc[0][2] += a.x * b.z; acc[0][3] += a.x * b.w;
            acc[1][0] += a.y * b.x; acc[1][1] += a.y * b.y; acc[1][2] += a.y * b.z; acc[1][3] += a.y * b.w;
            acc[2][0] += a.z * b.x; acc[2][1] += a.z * b.y; acc[2][2] += a.z * b.z; acc[2][3] += a.z * b.w;
            acc[3][0] += a.w * b.x; acc[3][1] += a.w * b.y; acc[3][2] += a.w * b.z; acc[3][3] += a.w * b.w;
        }
        __syncthreads();
    }

    const float* b1e = b1 + (size_t)e * D_FF;
#pragma unroll
    for (int i = 0; i < 4; i++) {
        int m = mBase + ty * 4 + i;
        if (m >= mEnd) continue;
        int n = n0 + tx * 4;
        float4 o;
        o.x = gelu_exact(acc[i][0] + b1e[n + 0]);
        o.y = gelu_exact(acc[i][1] + b1e[n + 1]);
        o.z = gelu_exact(acc[i][2] + b1e[n + 2]);
        o.w = gelu_exact(acc[i][3] + b1e[n + 3]);
        *(float4*)(g_H + (size_t)m * D_FF + n) = o;
    }
}

// GEMM2: out[token, d] += w[slot] * ( H[slot] @ W2[e] + b2[e] )
__global__ __launch_bounds__(256) void ffn2_kernel(const float* __restrict__ W2,
                                                   const float* __restrict__ b2,
                                                   float* __restrict__ out)
{
    int e = blockIdx.z;
    int mBase = g_off[e] + blockIdx.x * 64;
    int mEnd  = g_off[e + 1];
    if (mBase >= mEnd) return;
    int n0 = blockIdx.y * 64;

    __shared__ float As[16][64];
    __shared__ float Bs[16][64];
    __shared__ int   stok[64];
    __shared__ float sw[64];

    int tid = threadIdx.x;
    if (tid < 64) {
        int m = mBase + tid;
        if (m < mEnd) { stok[tid] = g_slot_token[m]; sw[tid] = g_slot_w[m]; }
        else          { stok[tid] = -1;              sw[tid] = 0.0f; }
    }
    __syncthreads();

    int ty = tid >> 4, tx = tid & 15;
    int ar = tid >> 2;
    int ac = (tid & 3) * 4;
    int br = tid >> 4;
    int bc = (tid & 15) * 4;

    bool rowValid = (mBase + ar) < mEnd;
    const float* Arow = g_H + (size_t)(mBase + ar) * D_FF;
    const float* W2e = W2 + (size_t)e * D_FF * D_MODEL;

    float acc[4][4];
#pragma unroll
    for (int i = 0; i < 4; i++)
#pragma unroll
        for (int j = 0; j < 4; j++) acc[i][j] = 0.0f;

    for (int k0 = 0; k0 < D_FF; k0 += 16) {
        float4 av = make_float4(0.f, 0.f, 0.f, 0.f);
        if (rowValid)
            av = *(const float4*)(Arow + k0 + ac);
        As[ac + 0][ar] = av.x; As[ac + 1][ar] = av.y;
        As[ac + 2][ar] = av.z; As[ac + 3][ar] = av.w;

        float4 bv = *(const float4*)(W2e + (size_t)(k0 + br) * D_MODEL + n0 + bc);
        *(float4*)&Bs[br][bc] = bv;
        __syncthreads();

#pragma unroll
        for (int kk = 0; kk < 16; kk++) {
            float4 a = *(float4*)&As[kk][ty * 4];
            float4 b = *(float4*)&Bs[kk][tx * 4];
            acc[0][0] += a.x * b.x; acc[0][1] += a.x * b.y; acc[0][2] += a.x * b.z; acc[0][3] += a.x * b.w;
            acc[1][0] += a.y * b.x; acc[1][1] += a.y * b.y; acc[1][2] += a.y * b.z; acc[1][3] += a.y * b.w;
            acc[2][0] += a.z * b.x; acc[2][1] += a.z * b.y; acc[2][2] += a.z * b.z; acc[2][3] += a.z * b.w;
            acc[3][0] += a.w * b.x; acc[3][1] += a.w * b.y; acc[3][2] += a.w * b.z; acc[3][3] += a.w * b.w;
        }
        __syncthreads();
    }

    const float* b2e = b2 + (size_t)e * D_MODEL;
#pragma unroll
    for (int i = 0; i < 4; i++) {
        int m = mBase + ty * 4 + i;
        if (m >= mEnd) continue;
        int tok = stok[ty * 4 + i];
        float w = sw[ty * 4 + i];
        int n = n0 + tx * 4;
#pragma unroll
        for (int j = 0; j < 4; j++) {
            float val = acc[i][j] + b2e[n + j];
            atomicAdd(&out[(size_t)tok * D_MODEL + n + j], w * val);
        }
    }
}

extern "C" void kernel_launch(void* const* d_in, const int* in_sizes, int n_in,
                              void* d_out, int out_size)
{
    const float* x  = (const float*)d_in[0];
    const float* Wg = (const float*)d_in[1];
    const float* bg = (const float*)d_in[2];
    const float* W1 = (const float*)d_in[3];
    const float* b1 = (const float*)d_in[4];
    const float* W2 = (const float*)d_in[5];
    const float* b2 = (const float*)d_in[6];
    float* out = (float*)d_out;

    // zero the combine region (atomics accumulate into it)
    cudaMemsetAsync(out, 0, (size_t)T_TOKENS * D_MODEL * sizeof(float));

    init_kernel<<<1, 32>>>();
    gate_kernel<<<T_TOKENS / 8, 256>>>(x, Wg, bg, out + (size_t)T_TOKENS * D_MODEL);
    prefix_kernel<<<1, 32>>>();
    scatter_kernel<<<T_TOKENS / 256, 256>>>();

    dim3 g1(T_TOKENS / 64, D_FF / 64, N_EXPERTS);
    ffn1_kernel<<<g1, 256>>>(x, W1, b1);

    dim3 g2(T_TOKENS / 64, D_MODEL / 64, N_EXPERTS);
    ffn2_kernel<<<g2, 256>>>(W2, b2, out);
}

// round 3
// speedup vs baseline: 1.7965x; 1.7965x over previous
#include <cuda_runtime.h>
#include <math.h>
#include <stdint.h>

#define D_MODEL   1024
#define N_EXPERTS 8
#define D_FF      4096
#define T_TOKENS  8192
#define TOTAL_SLOTS (T_TOKENS * 2)

#define BM 128
#define BN 128
#define BK 32
#define TILE_B (BM * BK * 4)          // 16 KB per tile buffer

// smem layout (dynamic)
#define SM_TMEM  0
#define SM_MBAR  16                   // two mbarriers @16, @24
#define SM_APTR  64                   // 128 x 8B row pointers
#define SM_TILES 2048                 // A0,A1,B0,B1 each 16KB, 1KB aligned
#define SMEM_TOTAL (SM_TILES + 4 * TILE_B)

// tf32 instruction descriptor: M=128, N=128, D=f32, A=B=tf32, K-major both
#define IDESC_TF32 ((8u << 24) | (16u << 17) | (2u << 10) | (2u << 7) | (1u << 4))

// Feature gate: tcgen05 only exists in the arch-specific (sm_103a) pass.
#if defined(__CUDA_ARCH__) && (defined(__CUDA_ARCH_FEAT_SM103_ALL) || defined(__CUDA_ARCH_FEAT_SM100_ALL) || defined(__CUDA_ARCH_FEAT_SM101_ALL))
#define USE_TCGEN05 1
#else
#define USE_TCGEN05 0
#endif

// ---------------- scratch (static __device__, allocation-free) ----------------
__device__ float g_H[(size_t)TOTAL_SLOTS * D_FF];        // 256 MB activations
__device__ float g_Y[(size_t)TOTAL_SLOTS * D_MODEL];     // 64 MB per-slot outputs
__device__ float g_W1t[(size_t)N_EXPERTS * D_FF * D_MODEL];  // 128 MB
__device__ float g_W2t[(size_t)N_EXPERTS * D_MODEL * D_FF];  // 128 MB
__device__ int   g_slot_token[TOTAL_SLOTS];
__device__ int   g_tok2slot[T_TOKENS * 2];
__device__ float g_topk_w[T_TOKENS * 2];
__device__ int   g_topk_idx[T_TOKENS * 2];
__device__ int   g_cnt[N_EXPERTS];
__device__ int   g_off[N_EXPERTS + 1];
__device__ int   g_cursor[N_EXPERTS];

// ---------------- small device helpers ----------------
__device__ __forceinline__ float gelu_exact(float h) {
    return 0.5f * h * (1.0f + erff(h * 0.70710678118654752440f));
}

__device__ __forceinline__ uint32_t smem_u32(const void* p) {
    uint32_t a;
    asm("{ .reg .u64 t; cvta.to.shared.u64 t, %1; cvt.u32.u64 %0, t; }" : "=r"(a) : "l"(p));
    return a;
}

#if USE_TCGEN05
__device__ __forceinline__ uint32_t elect_one() {
    uint32_t pred;
    asm volatile("{\n\t.reg .pred p;\n\telect.sync _|p, 0xFFFFFFFF;\n\t"
                 "selp.b32 %0, 1, 0, p;\n\t}" : "=r"(pred));
    return pred;
}

__device__ __forceinline__ uint32_t f2tf32(float f) {
    uint32_t u;
    asm("cvt.rna.tf32.f32 %0, %1;" : "=r"(u) : "f"(f));
    return u;
}

static __device__ __forceinline__ uint64_t make_desc_sw128(uint32_t addr) {
    const uint64_t base = (uint64_t(2) << 61) | (uint64_t(1) << 46) |
                          (uint64_t(64) << 32) | (uint64_t(1) << 16);
    return base | ((uint64_t)(addr >> 4) & 0x3FFF);
}

__device__ __forceinline__ void mbar_wait(uint32_t mbar, uint32_t parity) {
    uint32_t done;
    asm volatile("{\n\t.reg .pred p;\n\t"
        "mbarrier.try_wait.parity.acquire.cta.shared::cta.b64 p, [%1], %2;\n\t"
        "selp.b32 %0, 1, 0, p;\n\t}"
        : "=r"(done) : "r"(mbar), "r"(parity) : "memory");
    while (!done) {
        asm volatile("{\n\t.reg .pred p;\n\t"
            "mbarrier.try_wait.parity.acquire.cta.shared::cta.b64 p, [%1], %2, 0x989680;\n\t"
            "selp.b32 %0, 1, 0, p;\n\t}"
            : "=r"(done) : "r"(mbar), "r"(parity) : "memory");
    }
}

#define LDTM_X32(r, addr) \
    asm volatile( \
        "tcgen05.ld.sync.aligned.32x32b.x32.b32 " \
        "{%0, %1, %2, %3, %4, %5, %6, %7, " \
        " %8, %9, %10, %11, %12, %13, %14, %15, " \
        " %16, %17, %18, %19, %20, %21, %22, %23, " \
        " %24, %25, %26, %27, %28, %29, %30, %31}, [%32];" \
        : "=r"((r)[0]),  "=r"((r)[1]),  "=r"((r)[2]),  "=r"((r)[3]), \
          "=r"((r)[4]),  "=r"((r)[5]),  "=r"((r)[6]),  "=r"((r)[7]), \
          "=r"((r)[8]),  "=r"((r)[9]),  "=r"((r)[10]), "=r"((r)[11]), \
          "=r"((r)[12]), "=r"((r)[13]), "=r"((r)[14]), "=r"((r)[15]), \
          "=r"((r)[16]), "=r"((r)[17]), "=r"((r)[18]), "=r"((r)[19]), \
          "=r"((r)[20]), "=r"((r)[21]), "=r"((r)[22]), "=r"((r)[23]), \
          "=r"((r)[24]), "=r"((r)[25]), "=r"((r)[26]), "=r"((r)[27]), \
          "=r"((r)[28]), "=r"((r)[29]), "=r"((r)[30]), "=r"((r)[31]) \
        : "r"(addr))
#endif  // USE_TCGEN05

// ---------------- routing kernels ----------------
__global__ void init_kernel() {
    int i = threadIdx.x;
    if (i < N_EXPERTS) g_cnt[i] = 0;
}

__global__ void gate_kernel(const float* __restrict__ x,
                            const float* __restrict__ Wg,
                            const float* __restrict__ bg,
                            float* __restrict__ gate_out)
{
    int warp = threadIdx.x >> 5;
    int lane = threadIdx.x & 31;
    int t = blockIdx.x * (blockDim.x >> 5) + warp;
    if (t >= T_TOKENS) return;

    float acc[N_EXPERTS];
#pragma unroll
    for (int e = 0; e < N_EXPERTS; e++) acc[e] = 0.0f;

    const float* xr = x + (size_t)t * D_MODEL;
    for (int d = lane; d < D_MODEL; d += 32) {
        float xv = xr[d];
        const float4 w0 = *(const float4*)(Wg + (size_t)d * N_EXPERTS);
        const float4 w1 = *(const float4*)(Wg + (size_t)d * N_EXPERTS + 4);
        acc[0] += xv * w0.x; acc[1] += xv * w0.y;
        acc[2] += xv * w0.z; acc[3] += xv * w0.w;
        acc[4] += xv * w1.x; acc[5] += xv * w1.y;
        acc[6] += xv * w1.z; acc[7] += xv * w1.w;
    }
#pragma unroll
    for (int e = 0; e < N_EXPERTS; e++) {
#pragma unroll
        for (int o = 16; o > 0; o >>= 1)
            acc[e] += __shfl_xor_sync(0xffffffffu, acc[e], o);
    }

    if (lane == 0) {
        float logit[N_EXPERTS];
        float mx = -1e30f;
#pragma unroll
        for (int e = 0; e < N_EXPERTS; e++) {
            logit[e] = acc[e] + bg[e];
            gate_out[(size_t)t * N_EXPERTS + e] = logit[e];
            mx = fmaxf(mx, logit[e]);
        }
        float p[N_EXPERTS];
        float sum = 0.0f;
#pragma unroll
        for (int e = 0; e < N_EXPERTS; e++) { p[e] = expf(logit[e] - mx); sum += p[e]; }
        float inv = 1.0f / sum;
#pragma unroll
        for (int e = 0; e < N_EXPERTS; e++) p[e] *= inv;

        int i0 = 0; float v0 = p[0];
#pragma unroll
        for (int e = 1; e < N_EXPERTS; e++) if (p[e] > v0) { v0 = p[e]; i0 = e; }
        int i1 = -1; float v1 = -1e30f;
#pragma unroll
        for (int e = 0; e < N_EXPERTS; e++) {
            if (e == i0) continue;
            if (p[e] > v1) { v1 = p[e]; i1 = e; }
        }
        g_topk_idx[t * 2 + 0] = i0; g_topk_w[t * 2 + 0] = v0;
        g_topk_idx[t * 2 + 1] = i1; g_topk_w[t * 2 + 1] = v1;
        atomicAdd(&g_cnt[i0], 1);
        atomicAdd(&g_cnt[i1], 1);
    }
}

__global__ void prefix_kernel() {
    if (threadIdx.x == 0) {
        int s = 0;
        for (int e = 0; e < N_EXPERTS; e++) {
            g_off[e] = s;
            g_cursor[e] = s;
            s += g_cnt[e];
        }
        g_off[N_EXPERTS] = s;
    }
}

__global__ void scatter_kernel() {
    int t = blockIdx.x * blockDim.x + threadIdx.x;
    if (t >= T_TOKENS) return;
#pragma unroll
    for (int k = 0; k < 2; k++) {
        int e = g_topk_idx[t * 2 + k];
        int pos = atomicAdd(&g_cursor[e], 1);
        g_slot_token[pos] = t;
        g_tok2slot[t * 2 + k] = pos;
    }
}

// ---------------- weight transpose: in [z][R][C] -> out [z][C][R] ----------------
__global__ void transpose_kernel(const float* __restrict__ in, int R, int C, int which)
{
    __shared__ float tile[32][33];
    float* out = which ? g_W2t : g_W1t;
    size_t base = (size_t)blockIdx.z * (size_t)R * C;
    int c0 = blockIdx.x * 32, r0 = blockIdx.y * 32;
    int tx = threadIdx.x & 31, ty = threadIdx.x >> 5;
#pragma unroll
    for (int i = 0; i < 32; i += 8)
        tile[ty + i][tx] = in[base + (size_t)(r0 + ty + i) * C + (c0 + tx)];
    __syncthreads();
#pragma unroll
    for (int i = 0; i < 32; i += 8)
        out[base + (size_t)(c0 + ty + i) * R + (r0 + tx)] = tile[tx][ty + i];
}

// ---------------- grouped GEMM ----------------
// MODE 0: H[slot] = gelu(x[token[slot]] @ W1t^T + b1)   (K = D_MODEL, N = D_FF)
// MODE 1: Y[slot] = H[slot] @ W2t^T + b2                (K = D_FF,    N = D_MODEL)
// B matrices (g_W1t/g_W2t) are [N][K] row-major (K contiguous).
template<int KDIM, int MODE>
__global__ void __launch_bounds__(256, 1) moe_gemm(const float* __restrict__ x,
                                                   const float* __restrict__ bias)
{
    extern __shared__ char smem[];
    const int tid = threadIdx.x;
    const int wid = tid >> 5, lane = tid & 31;

    const int e = blockIdx.z;
    const int mBase = g_off[e] + blockIdx.x * BM;
    const int mEnd  = g_off[e + 1];
    if (mBase >= mEnd) return;
    const int n0 = blockIdx.y * BN;

    const float** sAptr = (const float**)(smem + SM_APTR);
    if (tid < BM) {
        int slot = mBase + tid;
        if (MODE == 0) {
            int tok = (slot < mEnd) ? g_slot_token[slot] : -1;
            sAptr[tid] = (tok >= 0) ? (x + (size_t)tok * D_MODEL) : (const float*)0;
        } else {
            sAptr[tid] = (slot < mEnd) ? (g_H + (size_t)slot * D_FF) : (const float*)0;
        }
    }
    const float* Be = (MODE == 0 ? g_W1t : g_W2t) + (size_t)e * (size_t)D_FF * D_MODEL;
    const int NB = (MODE == 0) ? D_FF : D_MODEL;
    const float* bb = bias + (size_t)e * NB + n0;

#if USE_TCGEN05
    const uint32_t sb = smem_u32(smem);
    if (wid == 0) {
        asm volatile("tcgen05.alloc.cta_group::1.sync.aligned.shared::cta.b32 [%0], %1;"
                     :: "r"(sb + SM_TMEM), "r"(128u) : "memory");
    }
    if (tid == 0) {
        asm volatile("mbarrier.init.shared.b64 [%0], 1;" :: "r"(sb + SM_MBAR) : "memory");
        asm volatile("mbarrier.init.shared.b64 [%0], 1;" :: "r"(sb + SM_MBAR + 8) : "memory");
    }
    __syncthreads();
    const uint32_t tmem = *(const uint32_t*)(smem + SM_TMEM);

    const int rb = tid >> 3;    // 0..31: base row handled by this thread
    const int c4 = tid & 7;     // float4 index within 32-float row

    const float* arow[4];
    const float* brow[4];
#pragma unroll
    for (int j = 0; j < 4; j++) {
        int r = rb + j * 32;
        arow[j] = sAptr[r];
        brow[j] = Be + (size_t)(n0 + r) * KDIM + c4 * 4;
    }

    constexpr int NT = KDIM / BK;
    int wp[2] = {0, 0};

    for (int kt = 0; kt < NT; kt++) {
        const int b = kt & 1;
        char* Ab = smem + SM_TILES + b * TILE_B;
        char* Bb = smem + SM_TILES + (2 + b) * TILE_B;
        if (kt >= 2) {
            mbar_wait(sb + SM_MBAR + b * 8, wp[b]);
            wp[b] ^= 1;
        }
        const int k0 = kt * BK;
#pragma unroll
        for (int j = 0; j < 4; j++) {
            const int r = rb + j * 32;
            const uint32_t off = (uint32_t)(r * 128 + c4 * 16);
            const uint32_t so  = off ^ ((off >> 3) & 0x70);
            float4 av = make_float4(0.f, 0.f, 0.f, 0.f);
            if (arow[j]) av = *(const float4*)(arow[j] + k0 + c4 * 4);
            uint4 au;
            au.x = f2tf32(av.x); au.y = f2tf32(av.y);
            au.z = f2tf32(av.z); au.w = f2tf32(av.w);
            *(uint4*)(Ab + so) = au;
            float4 bv = *(const float4*)(brow[j] + k0);
            uint4 bu;
            bu.x = f2tf32(bv.x); bu.y = f2tf32(bv.y);
            bu.z = f2tf32(bv.z); bu.w = f2tf32(bv.w);
            *(uint4*)(Bb + so) = bu;
        }
        __syncthreads();
        if (wid == 0) {
            if (elect_one()) {
                asm volatile("fence.proxy.async.shared::cta;" ::: "memory");
                uint64_t ad = make_desc_sw128(sb + SM_TILES + b * TILE_B);
                uint64_t bd = make_desc_sw128(sb + SM_TILES + (2 + b) * TILE_B);
#pragma unroll
                for (int s = 0; s < 4; s++) {
                    uint32_t en = (kt > 0 || s > 0) ? 1u : 0u;
                    asm volatile(
                        "{\n\t.reg .pred p;\n\tsetp.ne.u32 p, %4, 0;\n\t"
                        "tcgen05.mma.cta_group::1.kind::tf32 [%0], %1, %2, %3, p;\n\t}"
                        :: "r"(tmem), "l"(ad + s * 2), "l"(bd + s * 2),
                           "r"(IDESC_TF32), "r"(en)
                        : "memory");
                }
                asm volatile(
                    "tcgen05.commit.cta_group::1.mbarrier::arrive::one.shared::cluster.b64 [%0];"
                    :: "r"(sb + SM_MBAR + b * 8) : "memory");
            }
        }
    }

    // drain: MMAs on the same accumulator complete in-order; last commit suffices
    {
        const int bl = (NT - 1) & 1;
        mbar_wait(sb + SM_MBAR + bl * 8, wp[bl]);
        asm volatile("tcgen05.fence::after_thread_sync;" ::: "memory");
    }

    if (wid < 4) {
        const int row  = wid * 32 + lane;
        const int slot = mBase + row;
        float* dst = 0;
        if (slot < mEnd)
            dst = (MODE == 0) ? (g_H + (size_t)slot * D_FF + n0)
                              : (g_Y + (size_t)slot * D_MODEL + n0);
#pragma unroll
        for (int nb = 0; nb < 4; nb++) {
            uint32_t dr[32];
            LDTM_X32(dr, tmem + nb * 32);
            asm volatile("tcgen05.wait::ld.sync.aligned;" ::: "memory");
            if (dst) {
#pragma unroll
                for (int q = 0; q < 8; q++) {
                    float v0 = __uint_as_float(dr[q * 4 + 0]) + bb[nb * 32 + q * 4 + 0];
                    float v1 = __uint_as_float(dr[q * 4 + 1]) + bb[nb * 32 + q * 4 + 1];
                    float v2 = __uint_as_float(dr[q * 4 + 2]) + bb[nb * 32 + q * 4 + 2];
                    float v3 = __uint_as_float(dr[q * 4 + 3]) + bb[nb * 32 + q * 4 + 3];
                    if (MODE == 0) {
                        v0 = gelu_exact(v0); v1 = gelu_exact(v1);
                        v2 = gelu_exact(v2); v3 = gelu_exact(v3);
                    }
                    float4 o; o.x = v0; o.y = v1; o.z = v2; o.w = v3;
                    *(float4*)(dst + nb * 32 + q * 4) = o;
                }
            }
        }
    }
    __syncthreads();
    if (wid == 0) {
        asm volatile("tcgen05.relinquish_alloc_permit.cta_group::1.sync.aligned;");
        asm volatile("tcgen05.dealloc.cta_group::1.sync.aligned.b32 %0, %1;"
                     :: "r"(tmem), "r"(128u));
    }
#else
    // ---------- SIMT fallback (compiled only for the non-'a' PTX pass) ----------
    __syncthreads();
    float (*As)[132] = (float(*)[132])(smem + SM_TILES);              // [16][132]
    float (*Bs)[132] = (float(*)[132])(smem + SM_TILES + 16 * 132 * 4);

    const int ty = tid >> 4, tx = tid & 15;
    float acc[8][8];
#pragma unroll
    for (int i = 0; i < 8; i++)
#pragma unroll
        for (int j = 0; j < 8; j++) acc[i][j] = 0.0f;

    const int lr = tid >> 1;          // 0..127 load row
    const int lc = (tid & 1) * 8;     // 0 or 8 (two float4 per thread)
    const float* arow = sAptr[lr];
    const float* brow = Be + (size_t)(n0 + lr) * KDIM + lc;

    for (int k0 = 0; k0 < KDIM; k0 += 16) {
#pragma unroll
        for (int q = 0; q < 2; q++) {
            float4 av = make_float4(0.f, 0.f, 0.f, 0.f);
            if (arow) av = *(const float4*)(arow + k0 + lc + q * 4);
            As[lc + q * 4 + 0][lr] = av.x;
            As[lc + q * 4 + 1][lr] = av.y;
            As[lc + q * 4 + 2][lr] = av.z;
            As[lc + q * 4 + 3][lr] = av.w;
            float4 bv = *(const float4*)(brow + k0 + q * 4);
            Bs[lc + q * 4 + 0][lr] = bv.x;
            Bs[lc + q * 4 + 1][lr] = bv.y;
            Bs[lc + q * 4 + 2][lr] = bv.z;
            Bs[lc + q * 4 + 3][lr] = bv.w;
        }
        __syncthreads();
#pragma unroll
        for (int kk = 0; kk < 16; kk++) {
            float a[8], bfr[8];
#pragma unroll
            for (int i = 0; i < 8; i++) a[i] = As[kk][ty * 8 + i];
#pragma unroll
            for (int j = 0; j < 8; j++) bfr[j] = Bs[kk][tx * 8 + j];
#pragma unroll
            for (int i = 0; i < 8; i++)
#pragma unroll
                for (int j = 0; j < 8; j++) acc[i][j] += a[i] * bfr[j];
        }
        __syncthreads();
    }

#pragma unroll
    for (int i = 0; i < 8; i++) {
        int slot = mBase + ty * 8 + i;
        if (slot >= mEnd) continue;
        float* dst = (MODE == 0) ? (g_H + (size_t)slot * D_FF + n0)
                                 : (g_Y + (size_t)slot * D_MODEL + n0);
#pragma unroll
        for (int j = 0; j < 8; j++) {
            float v = acc[i][j] + bb[tx * 8 + j];
            if (MODE == 0) v = gelu_exact(v);
            dst[tx * 8 + j] = v;
        }
    }
#endif
}

// ---------------- final combine: out[t] = w0*Y[s0] + w1*Y[s1] ----------------
__global__ void combine_kernel(float* __restrict__ out) {
    int idx = blockIdx.x * blockDim.x + threadIdx.x;   // float4 index
    int t  = idx >> 8;                                  // 256 float4 per token
    int d4 = idx & 255;
    int s0 = g_tok2slot[t * 2 + 0], s1 = g_tok2slot[t * 2 + 1];
    float w0 = g_topk_w[t * 2 + 0], w1 = g_topk_w[t * 2 + 1];
    float4 a = *(const float4*)(g_Y + (size_t)s0 * D_MODEL + d4 * 4);
    float4 b = *(const float4*)(g_Y + (size_t)s1 * D_MODEL + d4 * 4);
    float4 o;
    o.x = w0 * a.x + w1 * b.x;
    o.y = w0 * a.y + w1 * b.y;
    o.z = w0 * a.z + w1 * b.z;
    o.w = w0 * a.w + w1 * b.w;
    *(float4*)(out + (size_t)t * D_MODEL + d4 * 4) = o;
}

// ---------------- host launch ----------------
extern "C" void kernel_launch(void* const* d_in, const int* in_sizes, int n_in,
                              void* d_out, int out_size)
{
    const float* x  = (const float*)d_in[0];
    const float* Wg = (const float*)d_in[1];
    const float* bg = (const float*)d_in[2];
    const float* W1 = (const float*)d_in[3];
    const float* b1 = (const float*)d_in[4];
    const float* W2 = (const float*)d_in[5];
    const float* b2 = (const float*)d_in[6];
    float* out = (float*)d_out;

    cudaFuncSetAttribute(moe_gemm<D_MODEL, 0>,
                         cudaFuncAttributeMaxDynamicSharedMemorySize, SMEM_TOTAL);
    cudaFuncSetAttribute(moe_gemm<D_FF, 1>,
                         cudaFuncAttributeMaxDynamicSharedMemorySize, SMEM_TOTAL);

    // weight transposes (every launch; deterministic)
    transpose_kernel<<<dim3(D_FF / 32, D_MODEL / 32, N_EXPERTS), 256>>>(W1, D_MODEL, D_FF, 0);
    transpose_kernel<<<dim3(D_MODEL / 32, D_FF / 32, N_EXPERTS), 256>>>(W2, D_FF, D_MODEL, 1);

    // routing
    init_kernel<<<1, 32>>>();
    gate_kernel<<<T_TOKENS / 8, 256>>>(x, Wg, bg, out + (size_t)T_TOKENS * D_MODEL);
    prefix_kernel<<<1, 32>>>();
    scatter_kernel<<<T_TOKENS / 256, 256>>>();

    // FFN GEMMs
    dim3 g1(T_TOKENS / BM, D_FF / BN, N_EXPERTS);      // overlaunched in x, early-exit
    moe_gemm<D_MODEL, 0><<<g1, 256, SMEM_TOTAL>>>(x, b1);

    dim3 g2(T_TOKENS / BM, D_MODEL / BN, N_EXPERTS);
    moe_gemm<D_FF, 1><<<g2, 256, SMEM_TOTAL>>>(x, b2);

    // combine
    combine_kernel<<<(T_TOKENS * 256) / 256, 256>>>(out);
}

// round 4
// speedup vs baseline: 8.9706x; 4.9933x over previous
#include <cuda_runtime.h>
#include <math.h>
#include <stdint.h>

#define D_MODEL   1024
#define N_EXPERTS 8
#define D_FF      4096
#define T_TOKENS  8192
#define TOTAL_SLOTS (T_TOKENS * 2)

#define BM 128
#define BN 256            // two 128-wide accumulators
#define BK 32
#define NSTAGE 4
#define TILE16K 16384
#define STAGE_B (3 * TILE16K)        // A + B0 + B1 per stage

// smem layout (dynamic)
#define SM_TMEM  0
#define SM_MBAR  16                  // empty[4] @16..48, done @48
#define SM_DONE  48
#define SM_TILES 2048
#define SMEM_TOTAL (SM_TILES + NSTAGE * STAGE_B)   // 198656 B

// tf32 idesc: M=128, N=128, f32 accum, tf32 a/b, K-major (validated round 3)
#define IDESC_TF32 ((8u << 24) | (16u << 17) | (2u << 10) | (2u << 7) | (1u << 4))

#if defined(__CUDA_ARCH__) && (defined(__CUDA_ARCH_FEAT_SM103_ALL) || defined(__CUDA_ARCH_FEAT_SM100_ALL) || defined(__CUDA_ARCH_FEAT_SM101_ALL))
#define USE_TCGEN05 1
#else
#define USE_TCGEN05 0
#endif

// ---------------- scratch (static __device__) ----------------
__device__ float g_A1[(size_t)(TOTAL_SLOTS + BM) * D_MODEL];     // gathered tf32 x
__device__ float g_H[(size_t)(TOTAL_SLOTS + BM) * D_FF];         // tf32 activations
__device__ float g_Y[(size_t)TOTAL_SLOTS * D_MODEL];
__device__ float g_W1t[(size_t)N_EXPERTS * D_FF * D_MODEL];      // [e][n][k] tf32
__device__ float g_W2t[(size_t)N_EXPERTS * D_MODEL * D_FF];      // [e][n][k] tf32
__device__ int   g_slot_token[TOTAL_SLOTS];
__device__ int   g_tok2slot[T_TOKENS * 2];
__device__ float g_topk_w[T_TOKENS * 2];
__device__ int   g_topk_idx[T_TOKENS * 2];
__device__ int   g_cnt[N_EXPERTS];
__device__ int   g_off[N_EXPERTS + 1];
__device__ int   g_cursor[N_EXPERTS];

// ---------------- helpers ----------------
__device__ __forceinline__ float gelu_exact(float h) {
    return 0.5f * h * (1.0f + erff(h * 0.70710678118654752440f));
}
__device__ __forceinline__ uint32_t smem_u32(const void* p) {
    uint32_t a;
    asm("{ .reg .u64 t; cvta.to.shared.u64 t, %1; cvt.u32.u64 %0, t; }" : "=r"(a) : "l"(p));
    return a;
}
__device__ __forceinline__ uint32_t f2tf32(float f) {
    uint32_t u;
    asm("cvt.rna.tf32.f32 %0, %1;" : "=r"(u) : "f"(f));
    return u;
}
__device__ __forceinline__ float f2tf32f(float f) { return __uint_as_float(f2tf32(f)); }

#if USE_TCGEN05
__device__ __forceinline__ uint32_t elect_one() {
    uint32_t pred;
    asm volatile("{\n\t.reg .pred p;\n\telect.sync _|p, 0xFFFFFFFF;\n\t"
                 "selp.b32 %0, 1, 0, p;\n\t}" : "=r"(pred));
    return pred;
}
static __device__ __forceinline__ uint64_t make_desc_sw128(uint32_t addr) {
    const uint64_t base = (uint64_t(2) << 61) | (uint64_t(1) << 46) |
                          (uint64_t(64) << 32) | (uint64_t(1) << 16);
    return base | ((uint64_t)(addr >> 4) & 0x3FFF);
}
__device__ __forceinline__ void mbar_wait(uint32_t mbar, uint32_t parity) {
    uint32_t done;
    asm volatile("{\n\t.reg .pred p;\n\t"
        "mbarrier.try_wait.parity.acquire.cta.shared::cta.b64 p, [%1], %2;\n\t"
        "selp.b32 %0, 1, 0, p;\n\t}"
        : "=r"(done) : "r"(mbar), "r"(parity) : "memory");
    while (!done) {
        asm volatile("{\n\t.reg .pred p;\n\t"
            "mbarrier.try_wait.parity.acquire.cta.shared::cta.b64 p, [%1], %2, 0x989680;\n\t"
            "selp.b32 %0, 1, 0, p;\n\t}"
            : "=r"(done) : "r"(mbar), "r"(parity) : "memory");
    }
}
#define CP_ASYNC16(dst, src) \
    asm volatile("cp.async.cg.shared.global [%0], [%1], 16;" :: "r"(dst), "l"(src))
#define CP_COMMIT() asm volatile("cp.async.commit_group;" ::: "memory")
#define CP_WAIT2()  asm volatile("cp.async.wait_group 2;" ::: "memory")

#define LDTM_X32(r, addr) \
    asm volatile( \
        "tcgen05.ld.sync.aligned.32x32b.x32.b32 " \
        "{%0, %1, %2, %3, %4, %5, %6, %7, " \
        " %8, %9, %10, %11, %12, %13, %14, %15, " \
        " %16, %17, %18, %19, %20, %21, %22, %23, " \
        " %24, %25, %26, %27, %28, %29, %30, %31}, [%32];" \
        : "=r"((r)[0]),  "=r"((r)[1]),  "=r"((r)[2]),  "=r"((r)[3]), \
          "=r"((r)[4]),  "=r"((r)[5]),  "=r"((r)[6]),  "=r"((r)[7]), \
          "=r"((r)[8]),  "=r"((r)[9]),  "=r"((r)[10]), "=r"((r)[11]), \
          "=r"((r)[12]), "=r"((r)[13]), "=r"((r)[14]), "=r"((r)[15]), \
          "=r"((r)[16]), "=r"((r)[17]), "=r"((r)[18]), "=r"((r)[19]), \
          "=r"((r)[20]), "=r"((r)[21]), "=r"((r)[22]), "=r"((r)[23]), \
          "=r"((r)[24]), "=r"((r)[25]), "=r"((r)[26]), "=r"((r)[27]), \
          "=r"((r)[28]), "=r"((r)[29]), "=r"((r)[30]), "=r"((r)[31]) \
        : "r"(addr))
#endif

// ---------------- routing kernels ----------------
__global__ void init_kernel() {
    int i = threadIdx.x;
    if (i < N_EXPERTS) g_cnt[i] = 0;
}

__global__ void gate_kernel(const float* __restrict__ x,
                            const float* __restrict__ Wg,
                            const float* __restrict__ bg,
                            float* __restrict__ gate_out)
{
    int warp = threadIdx.x >> 5;
    int lane = threadIdx.x & 31;
    int t = blockIdx.x * (blockDim.x >> 5) + warp;
    if (t >= T_TOKENS) return;

    float acc[N_EXPERTS];
#pragma unroll
    for (int e = 0; e < N_EXPERTS; e++) acc[e] = 0.0f;

    const float* xr = x + (size_t)t * D_MODEL;
    for (int d = lane; d < D_MODEL; d += 32) {
        float xv = xr[d];
        const float4 w0 = *(const float4*)(Wg + (size_t)d * N_EXPERTS);
        const float4 w1 = *(const float4*)(Wg + (size_t)d * N_EXPERTS + 4);
        acc[0] += xv * w0.x; acc[1] += xv * w0.y;
        acc[2] += xv * w0.z; acc[3] += xv * w0.w;
        acc[4] += xv * w1.x; acc[5] += xv * w1.y;
        acc[6] += xv * w1.z; acc[7] += xv * w1.w;
    }
#pragma unroll
    for (int e = 0; e < N_EXPERTS; e++) {
#pragma unroll
        for (int o = 16; o > 0; o >>= 1)
            acc[e] += __shfl_xor_sync(0xffffffffu, acc[e], o);
    }

    if (lane == 0) {
        float logit[N_EXPERTS];
        float mx = -1e30f;
#pragma unroll
        for (int e = 0; e < N_EXPERTS; e++) {
            logit[e] = acc[e] + bg[e];
            gate_out[(size_t)t * N_EXPERTS + e] = logit[e];
            mx = fmaxf(mx, logit[e]);
        }
        float p[N_EXPERTS];
        float sum = 0.0f;
#pragma unroll
        for (int e = 0; e < N_EXPERTS; e++) { p[e] = expf(logit[e] - mx); sum += p[e]; }
        float inv = 1.0f / sum;
#pragma unroll
        for (int e = 0; e < N_EXPERTS; e++) p[e] *= inv;

        int i0 = 0; float v0 = p[0];
#pragma unroll
        for (int e = 1; e < N_EXPERTS; e++) if (p[e] > v0) { v0 = p[e]; i0 = e; }
        int i1 = -1; float v1 = -1e30f;
#pragma unroll
        for (int e = 0; e < N_EXPERTS; e++) {
            if (e == i0) continue;
            if (p[e] > v1) { v1 = p[e]; i1 = e; }
        }
        g_topk_idx[t * 2 + 0] = i0; g_topk_w[t * 2 + 0] = v0;
        g_topk_idx[t * 2 + 1] = i1; g_topk_w[t * 2 + 1] = v1;
        atomicAdd(&g_cnt[i0], 1);
        atomicAdd(&g_cnt[i1], 1);
    }
}

__global__ void prefix_kernel() {
    if (threadIdx.x == 0) {
        int s = 0;
        for (int e = 0; e < N_EXPERTS; e++) {
            g_off[e] = s;
            g_cursor[e] = s;
            s += g_cnt[e];
        }
        g_off[N_EXPERTS] = s;
    }
}

__global__ void scatter_kernel() {
    int t = blockIdx.x * blockDim.x + threadIdx.x;
    if (t >= T_TOKENS) return;
#pragma unroll
    for (int k = 0; k < 2; k++) {
        int e = g_topk_idx[t * 2 + k];
        int pos = atomicAdd(&g_cursor[e], 1);
        g_slot_token[pos] = t;
        g_tok2slot[t * 2 + k] = pos;
    }
}

// gather + tf32-round x rows into slot order
__global__ void gather_kernel(const float* __restrict__ x) {
    int idx = blockIdx.x * blockDim.x + threadIdx.x;   // one float4 each
    int slot = idx >> 8;
    int c4 = idx & 255;
    int tok = g_slot_token[slot];
    float4 v = *(const float4*)(x + (size_t)tok * D_MODEL + c4 * 4);
    v.x = f2tf32f(v.x); v.y = f2tf32f(v.y);
    v.z = f2tf32f(v.z); v.w = f2tf32f(v.w);
    *(float4*)(g_A1 + (size_t)slot * D_MODEL + c4 * 4) = v;
}

// transpose + tf32 convert: in [z][R][C] -> out [z][C][R]
__global__ void transpose_kernel(const float* __restrict__ in, int R, int C, int which)
{
    __shared__ float tile[32][33];
    float* out = which ? g_W2t : g_W1t;
    size_t base = (size_t)blockIdx.z * (size_t)R * C;
    int c0 = blockIdx.x * 32, r0 = blockIdx.y * 32;
    int tx = threadIdx.x & 31, ty = threadIdx.x >> 5;
#pragma unroll
    for (int i = 0; i < 32; i += 8)
        tile[ty + i][tx] = in[base + (size_t)(r0 + ty + i) * C + (c0 + tx)];
    __syncthreads();
#pragma unroll
    for (int i = 0; i < 32; i += 8)
        out[base + (size_t)(c0 + ty + i) * R + (r0 + tx)] = f2tf32f(tile[tx][ty + i]);
}

// ---------------- grouped GEMM (tcgen05 tf32, cp.async 4-stage ring) ----------------
// MODE 0: H[slot] = tf32(gelu(A1[slot] @ W1t^T + b1))   K=D_MODEL, N=D_FF
// MODE 1: Y[slot] = H[slot] @ W2t^T + b2                K=D_FF,    N=D_MODEL
template<int KDIM, int MODE>
__global__ void __launch_bounds__(256, 1) moe_gemm(const float* __restrict__ bias)
{
    extern __shared__ char smem[];
    const int tid = threadIdx.x;
    const int wid = tid >> 5, lane = tid & 31;

    const int e = blockIdx.z;
    const int mBase = g_off[e] + blockIdx.x * BM;
    const int mEnd  = g_off[e + 1];
    if (mBase >= mEnd) return;
    const int n0 = blockIdx.y * BN;

    const float* Abase = (MODE == 0) ? g_A1 : g_H;
    const float* Bt    = (MODE == 0) ? g_W1t : g_W2t;
    const int NB = (MODE == 0) ? D_FF : D_MODEL;
    const size_t eRowB = (size_t)e * NB;   // B row index base

#if USE_TCGEN05
    const uint32_t sb = smem_u32(smem);
    if (wid == 0) {
        asm volatile("tcgen05.alloc.cta_group::1.sync.aligned.shared::cta.b32 [%0], %1;"
                     :: "r"(sb + SM_TMEM), "r"(256u) : "memory");
        asm volatile("tcgen05.relinquish_alloc_permit.cta_group::1.sync.aligned;");
    }
    if (tid == 0) {
#pragma unroll
        for (int s = 0; s < NSTAGE; s++)
            asm volatile("mbarrier.init.shared.b64 [%0], 1;"
                         :: "r"(sb + SM_MBAR + s * 8) : "memory");
        asm volatile("mbarrier.init.shared.b64 [%0], 1;" :: "r"(sb + SM_DONE) : "memory");
    }
    __syncthreads();
    const uint32_t tmem = *(const uint32_t*)(smem + SM_TMEM);

    // per-thread cp.async unit mapping (16B units within a 16KB tile: 1024 units)
    // A: 4 units, B0/B1: 4 units each per tile (2048 units across both)
    uint32_t dstA[4], dstB[8];
    const char* srcA[4];
    const char* srcB[8];
#pragma unroll
    for (int i = 0; i < 4; i++) {
        int u = tid + i * 256;
        int row = u >> 3, c16 = u & 7;
        uint32_t off = (uint32_t)(row * 128 + c16 * 16);
        uint32_t so = off ^ ((off >> 3) & 0x70);
        dstA[i] = so;
        srcA[i] = (const char*)(Abase + (size_t)(mBase + row) * KDIM) + c16 * 16;
    }
#pragma unroll
    for (int j = 0; j < 8; j++) {
        int u = tid + j * 256;       // 0..2047 across B0|B1
        int tile = u >> 10;          // 0 -> B0, 1 -> B1
        int v = u & 1023;
        int row = v >> 3, c16 = v & 7;
        uint32_t off = (uint32_t)(row * 128 + c16 * 16);
        uint32_t so = off ^ ((off >> 3) & 0x70);
        dstB[j] = (uint32_t)(tile + 1) * TILE16K + so;
        srcB[j] = (const char*)(Bt + (eRowB + n0 + tile * 128 + row) * (size_t)KDIM) + c16 * 16;
    }

    constexpr int NT = KDIM / BK;

    // prologue: load stages 0..NSTAGE-2
#pragma unroll
    for (int p = 0; p < NSTAGE - 1; p++) {
        uint32_t sbase = sb + SM_TILES + p * STAGE_B;
        size_t koff = (size_t)p * 128;   // BK*4 bytes
#pragma unroll
        for (int i = 0; i < 4; i++) CP_ASYNC16(sbase + dstA[i], srcA[i] + koff);
#pragma unroll
        for (int j = 0; j < 8; j++) CP_ASYNC16(sbase + dstB[j], srcB[j] + koff);
        CP_COMMIT();
    }

    for (int k = 0; k < NT; k++) {
        const int s = k & (NSTAGE - 1);
        CP_WAIT2();
        __syncthreads();

        if (wid == 0 && elect_one()) {
            asm volatile("fence.proxy.async.shared::cta;" ::: "memory");
            uint32_t stage = sb + SM_TILES + s * STAGE_B;
            uint64_t ad = make_desc_sw128(stage);
            uint64_t b0 = make_desc_sw128(stage + TILE16K);
            uint64_t b1 = make_desc_sw128(stage + 2 * TILE16K);
#pragma unroll
            for (int sub = 0; sub < 4; sub++) {
                uint32_t en = (k > 0 || sub > 0) ? 1u : 0u;
                asm volatile(
                    "{\n\t.reg .pred p;\n\tsetp.ne.u32 p, %4, 0;\n\t"
                    "tcgen05.mma.cta_group::1.kind::tf32 [%0], %1, %2, %3, p;\n\t}"
                    :: "r"(tmem), "l"(ad + sub * 2), "l"(b0 + sub * 2),
                       "r"(IDESC_TF32), "r"(en) : "memory");
                asm volatile(
                    "{\n\t.reg .pred p;\n\tsetp.ne.u32 p, %4, 0;\n\t"
                    "tcgen05.mma.cta_group::1.kind::tf32 [%0], %1, %2, %3, p;\n\t}"
                    :: "r"(tmem + 128), "l"(ad + sub * 2), "l"(b1 + sub * 2),
                       "r"(IDESC_TF32), "r"(en) : "memory");
            }
            asm volatile(
                "tcgen05.commit.cta_group::1.mbarrier::arrive::one.shared::cluster.b64 [%0];"
                :: "r"(sb + SM_MBAR + s * 8) : "memory");
        }

        const int pend = k + NSTAGE - 1;
        if (pend < NT) {
            if (pend >= NSTAGE) {
                uint32_t par = ((uint32_t)(pend / NSTAGE) - 1u) & 1u;
                mbar_wait(sb + SM_MBAR + (pend & (NSTAGE - 1)) * 8, par);
            }
            uint32_t sbase = sb + SM_TILES + (pend & (NSTAGE - 1)) * STAGE_B;
            size_t koff = (size_t)pend * 128;
#pragma unroll
            for (int i = 0; i < 4; i++) CP_ASYNC16(sbase + dstA[i], srcA[i] + koff);
#pragma unroll
            for (int j = 0; j < 8; j++) CP_ASYNC16(sbase + dstB[j], srcB[j] + koff);
        }
        CP_COMMIT();
    }

    if (wid == 0 && elect_one()) {
        asm volatile(
            "tcgen05.commit.cta_group::1.mbarrier::arrive::one.shared::cluster.b64 [%0];"
            :: "r"(sb + SM_DONE) : "memory");
    }
    mbar_wait(sb + SM_DONE, 0);
    asm volatile("tcgen05.fence::after_thread_sync;" ::: "memory");

    // epilogue: warps 0-3 -> D0 (cols n0..n0+127), warps 4-7 -> D1
    {
        const int half = wid >> 2;
        const int row = (wid & 3) * 32 + lane;
        const int slot = mBase + row;
        const float* bb = bias + (size_t)e * NB + n0 + half * 128;
        float* dst = 0;
        if (slot < mEnd)
            dst = (MODE == 0) ? (g_H + (size_t)slot * D_FF + n0 + half * 128)
                              : (g_Y + (size_t)slot * D_MODEL + n0 + half * 128);
        const uint32_t tm = tmem + half * 128;
#pragma unroll
        for (int nb = 0; nb < 4; nb++) {
            uint32_t dr[32];
            LDTM_X32(dr, tm + nb * 32);
            asm volatile("tcgen05.wait::ld.sync.aligned;" ::: "memory");
            if (dst) {
#pragma unroll
                for (int q = 0; q < 8; q++) {
                    float v0 = __uint_as_float(dr[q * 4 + 0]) + bb[nb * 32 + q * 4 + 0];
                    float v1 = __uint_as_float(dr[q * 4 + 1]) + bb[nb * 32 + q * 4 + 1];
                    float v2 = __uint_as_float(dr[q * 4 + 2]) + bb[nb * 32 + q * 4 + 2];
                    float v3 = __uint_as_float(dr[q * 4 + 3]) + bb[nb * 32 + q * 4 + 3];
                    if (MODE == 0) {
                        v0 = f2tf32f(gelu_exact(v0)); v1 = f2tf32f(gelu_exact(v1));
                        v2 = f2tf32f(gelu_exact(v2)); v3 = f2tf32f(gelu_exact(v3));
                    }
                    float4 o; o.x = v0; o.y = v1; o.z = v2; o.w = v3;
                    *(float4*)(dst + nb * 32 + q * 4) = o;
                }
            }
        }
    }
    __syncthreads();
    if (wid == 0) {
        asm volatile("tcgen05.dealloc.cta_group::1.sync.aligned.b32 %0, %1;"
                     :: "r"(tmem), "r"(256u));
    }
#else
    // ---------- SIMT fallback (non-'a' PTX pass; runtime uses the 'a' cubin) ----------
    __syncthreads();
    float (*As)[132] = (float(*)[132])(smem + SM_TILES);
    float (*Bs)[132] = (float(*)[132])(smem + SM_TILES + 16 * 132 * 4);
    const int ty = tid >> 4, tx = tid & 15;
    const int lr = tid >> 1;
    const int lc = (tid & 1) * 8;
    const float* arow = Abase + (size_t)(mBase + lr) * KDIM;

    for (int half = 0; half < 2; half++) {
        const int nh = n0 + half * 128;
        const float* brow = Bt + (eRowB + nh + lr) * (size_t)KDIM + lc;
        float acc[8][8];
#pragma unroll
        for (int i = 0; i < 8; i++)
#pragma unroll
            for (int j = 0; j < 8; j++) acc[i][j] = 0.0f;

        for (int k0 = 0; k0 < KDIM; k0 += 16) {
#pragma unroll
            for (int q = 0; q < 2; q++) {
                float4 av = *(const float4*)(arow + k0 + lc + q * 4);
                As[lc + q * 4 + 0][lr] = av.x;
                As[lc + q * 4 + 1][lr] = av.y;
                As[lc + q * 4 + 2][lr] = av.z;
                As[lc + q * 4 + 3][lr] = av.w;
                float4 bv = *(const float4*)(brow + k0 + q * 4);
                Bs[lc + q * 4 + 0][lr] = bv.x;
                Bs[lc + q * 4 + 1][lr] = bv.y;
                Bs[lc + q * 4 + 2][lr] = bv.z;
                Bs[lc + q * 4 + 3][lr] = bv.w;
            }
            __syncthreads();
#pragma unroll
            for (int kk = 0; kk < 16; kk++) {
                float a[8], bfr[8];
#pragma unroll
                for (int i = 0; i < 8; i++) a[i] = As[kk][ty * 8 + i];
#pragma unroll
                for (int j = 0; j < 8; j++) bfr[j] = Bs[kk][tx * 8 + j];
#pragma unroll
                for (int i = 0; i < 8; i++)
#pragma unroll
                    for (int j = 0; j < 8; j++) acc[i][j] += a[i] * bfr[j];
            }
            __syncthreads();
        }
        const float* bb = bias + (size_t)e * NB + nh;
#pragma unroll
        for (int i = 0; i < 8; i++) {
            int slot = mBase + ty * 8 + i;
            if (slot >= mEnd) continue;
            float* dst = (MODE == 0) ? (g_H + (size_t)slot * D_FF + nh)
                                     : (g_Y + (size_t)slot * D_MODEL + nh);
#pragma unroll
            for (int j = 0; j < 8; j++) {
                float v = acc[i][j] + bb[tx * 8 + j];
                if (MODE == 0) v = f2tf32f(gelu_exact(v));
                dst[tx * 8 + j] = v;
            }
        }
        __syncthreads();
    }
#endif
}

// ---------------- combine ----------------
__global__ void combine_kernel(float* __restrict__ out) {
    int idx = blockIdx.x * blockDim.x + threadIdx.x;
    int t  = idx >> 8;
    int d4 = idx & 255;
    int s0 = g_tok2slot[t * 2 + 0], s1 = g_tok2slot[t * 2 + 1];
    float w0 = g_topk_w[t * 2 + 0], w1 = g_topk_w[t * 2 + 1];
    float4 a = *(const float4*)(g_Y + (size_t)s0 * D_MODEL + d4 * 4);
    float4 b = *(const float4*)(g_Y + (size_t)s1 * D_MODEL + d4 * 4);
    float4 o;
    o.x = w0 * a.x + w1 * b.x;
    o.y = w0 * a.y + w1 * b.y;
    o.z = w0 * a.z + w1 * b.z;
    o.w = w0 * a.w + w1 * b.w;
    *(float4*)(out + (size_t)t * D_MODEL + d4 * 4) = o;
}

// ---------------- host launch ----------------
extern "C" void kernel_launch(void* const* d_in, const int* in_sizes, int n_in,
                              void* d_out, int out_size)
{
    const float* x  = (const float*)d_in[0];
    const float* Wg = (const float*)d_in[1];
    const float* bg = (const float*)d_in[2];
    const float* W1 = (const float*)d_in[3];
    const float* b1 = (const float*)d_in[4];
    const float* W2 = (const float*)d_in[5];
    const float* b2 = (const float*)d_in[6];
    float* out = (float*)d_out;

    cudaFuncSetAttribute(moe_gemm<D_MODEL, 0>,
                         cudaFuncAttributeMaxDynamicSharedMemorySize, SMEM_TOTAL);
    cudaFuncSetAttribute(moe_gemm<D_FF, 1>,
                         cudaFuncAttributeMaxDynamicSharedMemorySize, SMEM_TOTAL);

    transpose_kernel<<<dim3(D_FF / 32, D_MODEL / 32, N_EXPERTS), 256>>>(W1, D_MODEL, D_FF, 0);
    transpose_kernel<<<dim3(D_MODEL / 32, D_FF / 32, N_EXPERTS), 256>>>(W2, D_FF, D_MODEL, 1);

    init_kernel<<<1, 32>>>();
    gate_kernel<<<T_TOKENS / 8, 256>>>(x, Wg, bg, out + (size_t)T_TOKENS * D_MODEL);
    prefix_kernel<<<1, 32>>>();
    scatter_kernel<<<T_TOKENS / 256, 256>>>();
    gather_kernel<<<(TOTAL_SLOTS * 256) / 256, 256>>>(x);

    dim3 g1(TOTAL_SLOTS / BM, D_FF / BN, N_EXPERTS);      // 128 x 16 x 8
    moe_gemm<D_MODEL, 0><<<g1, 256, SMEM_TOTAL>>>(b1);

    dim3 g2(TOTAL_SLOTS / BM, D_MODEL / BN, N_EXPERTS);   // 128 x 4 x 8
    moe_gemm<D_FF, 1><<<g2, 256, SMEM_TOTAL>>>(b2);

    combine_kernel<<<(T_TOKENS * 256) / 256, 256>>>(out);
}

// round 5
// speedup vs baseline: 12.7843x; 1.4251x over previous
#include <cuda_runtime.h>
#include <cuda_fp16.h>
#include <math.h>
#include <stdint.h>

#define D_MODEL   1024
#define N_EXPERTS 8
#define D_FF      4096
#define T_TOKENS  8192
#define TOTAL_SLOTS (T_TOKENS * 2)

#define BM 128
#define BN 256            // two 128-wide accumulators
#define BK 64             // fp16: 128B smem row = 64 halfs
#define NSTAGE 4
#define TILE16K 16384
#define STAGE_B (3 * TILE16K)        // A + B0 + B1 per stage

// smem layout (dynamic)
#define SM_TMEM  0
#define SM_MBAR  16                  // empty[4] @16..48, done @48
#define SM_DONE  48
#define SM_TILES 2048
#define SMEM_TOTAL (SM_TILES + NSTAGE * STAGE_B)   // 198656 B

// fp16 idesc: M=128 (8<<24), N=128 (16<<17), f32 accum (1<<4), a/b = F16 (0)
#define IDESC_F16 ((8u << 24) | (16u << 17) | (1u << 4))

#if defined(__CUDA_ARCH__) && (defined(__CUDA_ARCH_FEAT_SM103_ALL) || defined(__CUDA_ARCH_FEAT_SM100_ALL) || defined(__CUDA_ARCH_FEAT_SM101_ALL))
#define USE_TCGEN05 1
#else
#define USE_TCGEN05 0
#endif

// ---------------- scratch (static __device__) ----------------
__device__ __half g_A1[(size_t)(TOTAL_SLOTS + BM) * D_MODEL];     // gathered fp16 x
__device__ __half g_H[(size_t)(TOTAL_SLOTS + BM) * D_FF];         // fp16 activations
__device__ float  g_Y[(size_t)TOTAL_SLOTS * D_MODEL];
__device__ __half g_W1t[(size_t)N_EXPERTS * D_FF * D_MODEL];      // [e][n][k] fp16
__device__ __half g_W2t[(size_t)N_EXPERTS * D_MODEL * D_FF];      // [e][n][k] fp16
__device__ int   g_slot_token[TOTAL_SLOTS];
__device__ int   g_tok2slot[T_TOKENS * 2];
__device__ float g_topk_w[T_TOKENS * 2];
__device__ int   g_topk_idx[T_TOKENS * 2];
__device__ int   g_cnt[N_EXPERTS];
__device__ int   g_off[N_EXPERTS + 1];
__device__ int   g_cursor[N_EXPERTS];

// ---------------- helpers ----------------
__device__ __forceinline__ float gelu_exact(float h) {
    return 0.5f * h * (1.0f + erff(h * 0.70710678118654752440f));
}
__device__ __forceinline__ uint32_t smem_u32(const void* p) {
    uint32_t a;
    asm("{ .reg .u64 t; cvta.to.shared.u64 t, %1; cvt.u32.u64 %0, t; }" : "=r"(a) : "l"(p));
    return a;
}

#if USE_TCGEN05
__device__ __forceinline__ uint32_t elect_one() {
    uint32_t pred;
    asm volatile("{\n\t.reg .pred p;\n\telect.sync _|p, 0xFFFFFFFF;\n\t"
                 "selp.b32 %0, 1, 0, p;\n\t}" : "=r"(pred));
    return pred;
}
static __device__ __forceinline__ uint64_t make_desc_sw128(uint32_t addr) {
    const uint64_t base = (uint64_t(2) << 61) | (uint64_t(1) << 46) |
                          (uint64_t(64) << 32) | (uint64_t(1) << 16);
    return base | ((uint64_t)(addr >> 4) & 0x3FFF);
}
__device__ __forceinline__ void mbar_wait(uint32_t mbar, uint32_t parity) {
    uint32_t done;
    asm volatile("{\n\t.reg .pred p;\n\t"
        "mbarrier.try_wait.parity.acquire.cta.shared::cta.b64 p, [%1], %2;\n\t"
        "selp.b32 %0, 1, 0, p;\n\t}"
        : "=r"(done) : "r"(mbar), "r"(parity) : "memory");
    while (!done) {
        asm volatile("{\n\t.reg .pred p;\n\t"
            "mbarrier.try_wait.parity.acquire.cta.shared::cta.b64 p, [%1], %2, 0x989680;\n\t"
            "selp.b32 %0, 1, 0, p;\n\t}"
            : "=r"(done) : "r"(mbar), "r"(parity) : "memory");
    }
}
#define CP_ASYNC16(dst, src) \
    asm volatile("cp.async.cg.shared.global [%0], [%1], 16;" :: "r"(dst), "l"(src))
#define CP_COMMIT() asm volatile("cp.async.commit_group;" ::: "memory")
#define CP_WAIT2()  asm volatile("cp.async.wait_group 2;" ::: "memory")

#define LDTM_X32(r, addr) \
    asm volatile( \
        "tcgen05.ld.sync.aligned.32x32b.x32.b32 " \
        "{%0, %1, %2, %3, %4, %5, %6, %7, " \
        " %8, %9, %10, %11, %12, %13, %14, %15, " \
        " %16, %17, %18, %19, %20, %21, %22, %23, " \
        " %24, %25, %26, %27, %28, %29, %30, %31}, [%32];" \
        : "=r"((r)[0]),  "=r"((r)[1]),  "=r"((r)[2]),  "=r"((r)[3]), \
          "=r"((r)[4]),  "=r"((r)[5]),  "=r"((r)[6]),  "=r"((r)[7]), \
          "=r"((r)[8]),  "=r"((r)[9]),  "=r"((r)[10]), "=r"((r)[11]), \
          "=r"((r)[12]), "=r"((r)[13]), "=r"((r)[14]), "=r"((r)[15]), \
          "=r"((r)[16]), "=r"((r)[17]), "=r"((r)[18]), "=r"((r)[19]), \
          "=r"((r)[20]), "=r"((r)[21]), "=r"((r)[22]), "=r"((r)[23]), \
          "=r"((r)[24]), "=r"((r)[25]), "=r"((r)[26]), "=r"((r)[27]), \
          "=r"((r)[28]), "=r"((r)[29]), "=r"((r)[30]), "=r"((r)[31]) \
        : "r"(addr))
#endif

// ---------------- routing kernels ----------------
__global__ void init_kernel() {
    int i = threadIdx.x;
    if (i < N_EXPERTS) g_cnt[i] = 0;
}

__global__ void gate_kernel(const float* __restrict__ x,
                            const float* __restrict__ Wg,
                            const float* __restrict__ bg,
                            float* __restrict__ gate_out)
{
    int warp = threadIdx.x >> 5;
    int lane = threadIdx.x & 31;
    int t = blockIdx.x * (blockDim.x >> 5) + warp;
    if (t >= T_TOKENS) return;

    float acc[N_EXPERTS];
#pragma unroll
    for (int e = 0; e < N_EXPERTS; e++) acc[e] = 0.0f;

    const float* xr = x + (size_t)t * D_MODEL;
    for (int d = lane; d < D_MODEL; d += 32) {
        float xv = xr[d];
        const float4 w0 = *(const float4*)(Wg + (size_t)d * N_EXPERTS);
        const float4 w1 = *(const float4*)(Wg + (size_t)d * N_EXPERTS + 4);
        acc[0] += xv * w0.x; acc[1] += xv * w0.y;
        acc[2] += xv * w0.z; acc[3] += xv * w0.w;
        acc[4] += xv * w1.x; acc[5] += xv * w1.y;
        acc[6] += xv * w1.z; acc[7] += xv * w1.w;
    }
#pragma unroll
    for (int e = 0; e < N_EXPERTS; e++) {
#pragma unroll
        for (int o = 16; o > 0; o >>= 1)
            acc[e] += __shfl_xor_sync(0xffffffffu, acc[e], o);
    }

    if (lane == 0) {
        float logit[N_EXPERTS];
        float mx = -1e30f;
#pragma unroll
        for (int e = 0; e < N_EXPERTS; e++) {
            logit[e] = acc[e] + bg[e];
            gate_out[(size_t)t * N_EXPERTS + e] = logit[e];
            mx = fmaxf(mx, logit[e]);
        }
        float p[N_EXPERTS];
        float sum = 0.0f;
#pragma unroll
        for (int e = 0; e < N_EXPERTS; e++) { p[e] = expf(logit[e] - mx); sum += p[e]; }
        float inv = 1.0f / sum;
#pragma unroll
        for (int e = 0; e < N_EXPERTS; e++) p[e] *= inv;

        int i0 = 0; float v0 = p[0];
#pragma unroll
        for (int e = 1; e < N_EXPERTS; e++) if (p[e] > v0) { v0 = p[e]; i0 = e; }
        int i1 = -1; float v1 = -1e30f;
#pragma unroll
        for (int e = 0; e < N_EXPERTS; e++) {
            if (e == i0) continue;
            if (p[e] > v1) { v1 = p[e]; i1 = e; }
        }
        g_topk_idx[t * 2 + 0] = i0; g_topk_w[t * 2 + 0] = v0;
        g_topk_idx[t * 2 + 1] = i1; g_topk_w[t * 2 + 1] = v1;
        atomicAdd(&g_cnt[i0], 1);
        atomicAdd(&g_cnt[i1], 1);
    }
}

__global__ void prefix_kernel() {
    if (threadIdx.x == 0) {
        int s = 0;
        for (int e = 0; e < N_EXPERTS; e++) {
            g_off[e] = s;
            g_cursor[e] = s;
            s += g_cnt[e];
        }
        g_off[N_EXPERTS] = s;
    }
}

__global__ void scatter_kernel() {
    int t = blockIdx.x * blockDim.x + threadIdx.x;
    if (t >= T_TOKENS) return;
#pragma unroll
    for (int k = 0; k < 2; k++) {
        int e = g_topk_idx[t * 2 + k];
        int pos = atomicAdd(&g_cursor[e], 1);
        g_slot_token[pos] = t;
        g_tok2slot[t * 2 + k] = pos;
    }
}

// gather + fp16-convert x rows into slot order (one float4 -> 4 halfs per thread)
__global__ void gather_kernel(const float* __restrict__ x) {
    int idx = blockIdx.x * blockDim.x + threadIdx.x;
    int slot = idx >> 8;
    int c4 = idx & 255;
    int tok = g_slot_token[slot];
    float4 v = *(const float4*)(x + (size_t)tok * D_MODEL + c4 * 4);
    __half2 h0 = __floats2half2_rn(v.x, v.y);
    __half2 h1 = __floats2half2_rn(v.z, v.w);
    uint2 pk = make_uint2(*(uint32_t*)&h0, *(uint32_t*)&h1);
    *(uint2*)(g_A1 + (size_t)slot * D_MODEL + c4 * 4) = pk;
}

// transpose + fp16 convert: in [z][R][C] fp32 -> out [z][C][R] fp16
__global__ void transpose_kernel(const float* __restrict__ in, int R, int C, int which)
{
    __shared__ float tile[32][33];
    __half* out = which ? g_W2t : g_W1t;
    size_t base = (size_t)blockIdx.z * (size_t)R * C;
    int c0 = blockIdx.x * 32, r0 = blockIdx.y * 32;
    int tx = threadIdx.x & 31, ty = threadIdx.x >> 5;
#pragma unroll
    for (int i = 0; i < 32; i += 8)
        tile[ty + i][tx] = in[base + (size_t)(r0 + ty + i) * C + (c0 + tx)];
    __syncthreads();
    // 512 half2 writes, 2 per thread: idx -> (c = idx>>4, rpair = idx&15)
#pragma unroll
    for (int q = 0; q < 2; q++) {
        int idx = threadIdx.x * 2 + q;
        int c = idx >> 4;
        int p = idx & 15;
        __half2 v = __floats2half2_rn(tile[2 * p][c], tile[2 * p + 1][c]);
        *(__half2*)(out + base + (size_t)(c0 + c) * R + (r0 + 2 * p)) = v;
    }
}

// ---------------- grouped GEMM (tcgen05 fp16, cp.async 4-stage ring) ----------------
// MODE 0: H[slot] = fp16(gelu(A1[slot] @ W1t^T + b1))   K=D_MODEL, N=D_FF
// MODE 1: Y[slot] = H[slot] @ W2t^T + b2  (fp32 out)    K=D_FF,    N=D_MODEL
template<int KDIM, int MODE>
__global__ void __launch_bounds__(256, 1) moe_gemm(const float* __restrict__ bias)
{
    extern __shared__ char smem[];
    const int tid = threadIdx.x;
    const int wid = tid >> 5, lane = tid & 31;

    const int e = blockIdx.z;
    const int mBase = g_off[e] + blockIdx.x * BM;
    const int mEnd  = g_off[e + 1];
    if (mBase >= mEnd) return;
    const int n0 = blockIdx.y * BN;

    const __half* Abase = (MODE == 0) ? g_A1 : g_H;
    const __half* Bt    = (MODE == 0) ? g_W1t : g_W2t;
    const int NB = (MODE == 0) ? D_FF : D_MODEL;
    const size_t eRowB = (size_t)e * NB;

#if USE_TCGEN05
    const uint32_t sb = smem_u32(smem);
    if (wid == 0) {
        asm volatile("tcgen05.alloc.cta_group::1.sync.aligned.shared::cta.b32 [%0], %1;"
                     :: "r"(sb + SM_TMEM), "r"(256u) : "memory");
        asm volatile("tcgen05.relinquish_alloc_permit.cta_group::1.sync.aligned;");
    }
    if (tid == 0) {
#pragma unroll
        for (int s = 0; s < NSTAGE; s++)
            asm volatile("mbarrier.init.shared.b64 [%0], 1;"
                         :: "r"(sb + SM_MBAR + s * 8) : "memory");
        asm volatile("mbarrier.init.shared.b64 [%0], 1;" :: "r"(sb + SM_DONE) : "memory");
    }
    __syncthreads();
    const uint32_t tmem = *(const uint32_t*)(smem + SM_TMEM);

    // cp.async mapping: 16KB tile = 1024 16B units = 128 rows x 8 units (64 halfs/row)
    uint32_t dstA[4], dstB[8];
    const char* srcA[4];
    const char* srcB[8];
#pragma unroll
    for (int i = 0; i < 4; i++) {
        int u = tid + i * 256;
        int row = u >> 3, c16 = u & 7;
        uint32_t off = (uint32_t)(row * 128 + c16 * 16);
        uint32_t so = off ^ ((off >> 3) & 0x70);
        dstA[i] = so;
        srcA[i] = (const char*)(Abase + (size_t)(mBase + row) * KDIM) + c16 * 16;
    }
#pragma unroll
    for (int j = 0; j < 8; j++) {
        int u = tid + j * 256;
        int tile = u >> 10;
        int v = u & 1023;
        int row = v >> 3, c16 = v & 7;
        uint32_t off = (uint32_t)(row * 128 + c16 * 16);
        uint32_t so = off ^ ((off >> 3) & 0x70);
        dstB[j] = (uint32_t)(tile + 1) * TILE16K + so;
        srcB[j] = (const char*)(Bt + (eRowB + n0 + tile * 128 + row) * (size_t)KDIM) + c16 * 16;
    }

    constexpr int NT = KDIM / BK;

#pragma unroll
    for (int p = 0; p < NSTAGE - 1; p++) {
        uint32_t sbase = sb + SM_TILES + p * STAGE_B;
        size_t koff = (size_t)p * 128;   // BK halfs = 128 bytes
#pragma unroll
        for (int i = 0; i < 4; i++) CP_ASYNC16(sbase + dstA[i], srcA[i] + koff);
#pragma unroll
        for (int j = 0; j < 8; j++) CP_ASYNC16(sbase + dstB[j], srcB[j] + koff);
        CP_COMMIT();
    }

    for (int k = 0; k < NT; k++) {
        const int s = k & (NSTAGE - 1);
        CP_WAIT2();
        __syncthreads();

        if (wid == 0 && elect_one()) {
            asm volatile("fence.proxy.async.shared::cta;" ::: "memory");
            uint32_t stage = sb + SM_TILES + s * STAGE_B;
            uint64_t ad = make_desc_sw128(stage);
            uint64_t b0 = make_desc_sw128(stage + TILE16K);
            uint64_t b1 = make_desc_sw128(stage + 2 * TILE16K);
#pragma unroll
            for (int sub = 0; sub < 4; sub++) {       // 4 x K=16 fp16 steps = BK 64
                uint32_t en = (k > 0 || sub > 0) ? 1u : 0u;
                asm volatile(
                    "{\n\t.reg .pred p;\n\tsetp.ne.u32 p, %4, 0;\n\t"
                    "tcgen05.mma.cta_group::1.kind::f16 [%0], %1, %2, %3, "
                    "{%5, %5, %5, %5}, p;\n\t}"
                    :: "r"(tmem), "l"(ad + sub * 2), "l"(b0 + sub * 2),
                       "r"(IDESC_F16), "r"(en), "r"(0u) : "memory");
                asm volatile(
                    "{\n\t.reg .pred p;\n\tsetp.ne.u32 p, %4, 0;\n\t"
                    "tcgen05.mma.cta_group::1.kind::f16 [%0], %1, %2, %3, "
                    "{%5, %5, %5, %5}, p;\n\t}"
                    :: "r"(tmem + 128), "l"(ad + sub * 2), "l"(b1 + sub * 2),
                       "r"(IDESC_F16), "r"(en), "r"(0u) : "memory");
            }
            asm volatile(
                "tcgen05.commit.cta_group::1.mbarrier::arrive::one.shared::cluster.b64 [%0];"
                :: "r"(sb + SM_MBAR + s * 8) : "memory");
        }

        const int pend = k + NSTAGE - 1;
        if (pend < NT) {
            if (pend >= NSTAGE) {
                uint32_t par = ((uint32_t)(pend / NSTAGE) - 1u) & 1u;
                mbar_wait(sb + SM_MBAR + (pend & (NSTAGE - 1)) * 8, par);
            }
            uint32_t sbase = sb + SM_TILES + (pend & (NSTAGE - 1)) * STAGE_B;
            size_t koff = (size_t)pend * 128;
#pragma unroll
            for (int i = 0; i < 4; i++) CP_ASYNC16(sbase + dstA[i], srcA[i] + koff);
#pragma unroll
            for (int j = 0; j < 8; j++) CP_ASYNC16(sbase + dstB[j], srcB[j] + koff);
        }
        CP_COMMIT();
    }

    if (wid == 0 && elect_one()) {
        asm volatile(
            "tcgen05.commit.cta_group::1.mbarrier::arrive::one.shared::cluster.b64 [%0];"
            :: "r"(sb + SM_DONE) : "memory");
    }
    mbar_wait(sb + SM_DONE, 0);
    asm volatile("tcgen05.fence::after_thread_sync;" ::: "memory");

    // epilogue: warps 0-3 -> D0 (cols n0..n0+127), warps 4-7 -> D1
    {
        const int half = wid >> 2;
        const int row = (wid & 3) * 32 + lane;
        const int slot = mBase + row;
        const float* bb = bias + (size_t)e * NB + n0 + half * 128;
        const uint32_t tm = tmem + half * 128;
        bool valid = slot < mEnd;
        __half* dstH = valid ? (g_H + (size_t)slot * D_FF + n0 + half * 128) : (__half*)0;
        float*  dstY = valid ? (g_Y + (size_t)slot * D_MODEL + n0 + half * 128) : (float*)0;
#pragma unroll
        for (int nb = 0; nb < 4; nb++) {
            uint32_t dr[32];
            LDTM_X32(dr, tm + nb * 32);
            asm volatile("tcgen05.wait::ld.sync.aligned;" ::: "memory");
            if (valid) {
#pragma unroll
                for (int q = 0; q < 8; q++) {
                    float v0 = __uint_as_float(dr[q * 4 + 0]) + bb[nb * 32 + q * 4 + 0];
                    float v1 = __uint_as_float(dr[q * 4 + 1]) + bb[nb * 32 + q * 4 + 1];
                    float v2 = __uint_as_float(dr[q * 4 + 2]) + bb[nb * 32 + q * 4 + 2];
                    float v3 = __uint_as_float(dr[q * 4 + 3]) + bb[nb * 32 + q * 4 + 3];
                    if (MODE == 0) {
                        __half2 h0 = __floats2half2_rn(gelu_exact(v0), gelu_exact(v1));
                        __half2 h1 = __floats2half2_rn(gelu_exact(v2), gelu_exact(v3));
                        uint2 pk = make_uint2(*(uint32_t*)&h0, *(uint32_t*)&h1);
                        *(uint2*)(dstH + nb * 32 + q * 4) = pk;
                    } else {
                        float4 o; o.x = v0; o.y = v1; o.z = v2; o.w = v3;
                        *(float4*)(dstY + nb * 32 + q * 4) = o;
                    }
                }
            }
        }
    }
    __syncthreads();
    if (wid == 0) {
        asm volatile("tcgen05.dealloc.cta_group::1.sync.aligned.b32 %0, %1;"
                     :: "r"(tmem), "r"(256u));
    }
#else
    // ---------- SIMT fallback (non-'a' PTX pass only; runtime uses the 'a' cubin) ----------
    __syncthreads();
    float (*As)[132] = (float(*)[132])(smem + SM_TILES);
    float (*Bs)[132] = (float(*)[132])(smem + SM_TILES + 16 * 132 * 4);
    const int ty = tid >> 4, tx = tid & 15;
    const int lr = tid >> 1;
    const int lc = (tid & 1) * 8;
    const __half* arow = Abase + (size_t)(mBase + lr) * KDIM;

    for (int half = 0; half < 2; half++) {
        const int nh = n0 + half * 128;
        const __half* brow = Bt + (eRowB + nh + lr) * (size_t)KDIM + lc;
        float acc[8][8];
#pragma unroll
        for (int i = 0; i < 8; i++)
#pragma unroll
            for (int j = 0; j < 8; j++) acc[i][j] = 0.0f;

        for (int k0 = 0; k0 < KDIM; k0 += 16) {
#pragma unroll
            for (int q = 0; q < 8; q++) {
                As[lc + q][lr] = __half2float(arow[k0 + lc + q]);
                Bs[lc + q][lr] = __half2float(brow[k0 + q]);
            }
            __syncthreads();
#pragma unroll
            for (int kk = 0; kk < 16; kk++) {
                float a[8], bfr[8];
#pragma unroll
                for (int i = 0; i < 8; i++) a[i] = As[kk][ty * 8 + i];
#pragma unroll
                for (int j = 0; j < 8; j++) bfr[j] = Bs[kk][tx * 8 + j];
#pragma unroll
                for (int i = 0; i < 8; i++)
#pragma unroll
                    for (int j = 0; j < 8; j++) acc[i][j] += a[i] * bfr[j];
            }
            __syncthreads();
        }
        const float* bb = bias + (size_t)e * NB + nh;
#pragma unroll
        for (int i = 0; i < 8; i++) {
            int slot = mBase + ty * 8 + i;
            if (slot >= mEnd) continue;
#pragma unroll
            for (int j = 0; j < 8; j++) {
                float v = acc[i][j] + bb[tx * 8 + j];
                if (MODE == 0)
                    g_H[(size_t)slot * D_FF + nh + tx * 8 + j] = __float2half_rn(gelu_exact(v));
                else
                    g_Y[(size_t)slot * D_MODEL + nh + tx * 8 + j] = v;
            }
        }
        __syncthreads();
    }
#endif
}

// ---------------- combine ----------------
__global__ void combine_kernel(float* __restrict__ out) {
    int idx = blockIdx.x * blockDim.x + threadIdx.x;
    int t  = idx >> 8;
    int d4 = idx & 255;
    int s0 = g_tok2slot[t * 2 + 0], s1 = g_tok2slot[t * 2 + 1];
    float w0 = g_topk_w[t * 2 + 0], w1 = g_topk_w[t * 2 + 1];
    float4 a = *(const float4*)(g_Y + (size_t)s0 * D_MODEL + d4 * 4);
    float4 b = *(const float4*)(g_Y + (size_t)s1 * D_MODEL + d4 * 4);
    float4 o;
    o.x = w0 * a.x + w1 * b.x;
    o.y = w0 * a.y + w1 * b.y;
    o.z = w0 * a.z + w1 * b.z;
    o.w = w0 * a.w + w1 * b.w;
    *(float4*)(out + (size_t)t * D_MODEL + d4 * 4) = o;
}

// ---------------- host launch ----------------
extern "C" void kernel_launch(void* const* d_in, const int* in_sizes, int n_in,
                              void* d_out, int out_size)
{
    const float* x  = (const float*)d_in[0];
    const float* Wg = (const float*)d_in[1];
    const float* bg = (const float*)d_in[2];
    const float* W1 = (const float*)d_in[3];
    const float* b1 = (const float*)d_in[4];
    const float* W2 = (const float*)d_in[5];
    const float* b2 = (const float*)d_in[6];
    float* out = (float*)d_out;

    cudaFuncSetAttribute(moe_gemm<D_MODEL, 0>,
                         cudaFuncAttributeMaxDynamicSharedMemorySize, SMEM_TOTAL);
    cudaFuncSetAttribute(moe_gemm<D_FF, 1>,
                         cudaFuncAttributeMaxDynamicSharedMemorySize, SMEM_TOTAL);

    transpose_kernel<<<dim3(D_FF / 32, D_MODEL / 32, N_EXPERTS), 256>>>(W1, D_MODEL, D_FF, 0);
    transpose_kernel<<<dim3(D_MODEL / 32, D_FF / 32, N_EXPERTS), 256>>>(W2, D_FF, D_MODEL, 1);

    init_kernel<<<1, 32>>>();
    gate_kernel<<<T_TOKENS / 8, 256>>>(x, Wg, bg, out + (size_t)T_TOKENS * D_MODEL);
    prefix_kernel<<<1, 32>>>();
    scatter_kernel<<<T_TOKENS / 256, 256>>>();
    gather_kernel<<<(TOTAL_SLOTS * 256) / 256, 256>>>(x);

    dim3 g1(TOTAL_SLOTS / BM, D_FF / BN, N_EXPERTS);      // 128 x 16 x 8 (early-exit x)
    moe_gemm<D_MODEL, 0><<<g1, 256, SMEM_TOTAL>>>(b1);

    dim3 g2(TOTAL_SLOTS / BM, D_MODEL / BN, N_EXPERTS);   // 128 x 4 x 8
    moe_gemm<D_FF, 1><<<g2, 256, SMEM_TOTAL>>>(b2);

    combine_kernel<<<(T_TOKENS * 256) / 256, 256>>>(out);
}

// round 11
// speedup vs baseline: 13.5380x; 1.0590x over previous
#include <cuda_runtime.h>
#include <cuda_fp16.h>
#include <math.h>
#include <stdint.h>

#define D_MODEL   1024
#define N_EXPERTS 8
#define D_FF      4096
#define T_TOKENS  8192
#define TOTAL_SLOTS (T_TOKENS * 2)

#define BM 256            // two 128-row A tiles
#define BN 256            // two 128-col B tiles
#define BK 64             // fp16: 128B smem row = 64 halfs
#define NSTAGE 3
#define TILE16K 16384
#define STAGE_B (4 * TILE16K)        // A0 + A1 + B0 + B1 per stage

// smem layout (dynamic)
#define SM_TMEM  0
#define SM_MBAR  16                  // empty[NSTAGE] @16.., done after
#define SM_DONE  (SM_MBAR + NSTAGE * 8)
#define SM_TILES 2048
#define SMEM_TOTAL (SM_TILES + NSTAGE * STAGE_B)   // 198656 B

// fp16 idesc: M=128 (8<<24), N=128 (16<<17), f32 accum (1<<4), a/b = F16 (0)
#define IDESC_F16 ((8u << 24) | (16u << 17) | (1u << 4))

#if defined(__CUDA_ARCH__) && (defined(__CUDA_ARCH_FEAT_SM103_ALL) || defined(__CUDA_ARCH_FEAT_SM100_ALL) || defined(__CUDA_ARCH_FEAT_SM101_ALL))
#define USE_TCGEN05 1
#else
#define USE_TCGEN05 0
#endif

// ---------------- scratch (static __device__) ----------------
__device__ __half g_A1[(size_t)(TOTAL_SLOTS + BM) * D_MODEL];     // gathered fp16 x
__device__ __half g_H[(size_t)(TOTAL_SLOTS + BM) * D_FF];         // fp16 activations
__device__ float  g_Y[(size_t)TOTAL_SLOTS * D_MODEL];
__device__ __half g_W1t[(size_t)N_EXPERTS * D_FF * D_MODEL];      // [e][n][k] fp16
__device__ __half g_W2t[(size_t)N_EXPERTS * D_MODEL * D_FF];      // [e][n][k] fp16
__device__ int   g_slot_token[TOTAL_SLOTS];
__device__ int   g_tok2slot[T_TOKENS * 2];
__device__ float g_topk_w[T_TOKENS * 2];
__device__ int   g_topk_idx[T_TOKENS * 2];
__device__ int   g_cnt[N_EXPERTS];
__device__ int   g_off[N_EXPERTS + 1];
__device__ int   g_cursor[N_EXPERTS];

// ---------------- helpers ----------------
__device__ __forceinline__ float gelu_exact(float h) {
    return 0.5f * h * (1.0f + erff(h * 0.70710678118654752440f));
}
__device__ __forceinline__ uint32_t smem_u32(const void* p) {
    uint32_t a;
    asm("{ .reg .u64 t; cvta.to.shared.u64 t, %1; cvt.u32.u64 %0, t; }" : "=r"(a) : "l"(p));
    return a;
}

#if USE_TCGEN05
__device__ __forceinline__ uint32_t elect_one() {
    uint32_t pred;
    asm volatile("{\n\t.reg .pred p;\n\telect.sync _|p, 0xFFFFFFFF;\n\t"
                 "selp.b32 %0, 1, 0, p;\n\t}" : "=r"(pred));
    return pred;
}
static __device__ __forceinline__ uint64_t make_desc_sw128(uint32_t addr) {
    const uint64_t base = (uint64_t(2) << 61) | (uint64_t(1) << 46) |
                          (uint64_t(64) << 32) | (uint64_t(1) << 16);
    return base | ((uint64_t)(addr >> 4) & 0x3FFF);
}
__device__ __forceinline__ void mbar_wait(uint32_t mbar, uint32_t parity) {
    uint32_t done;
    asm volatile("{\n\t.reg .pred p;\n\t"
        "mbarrier.try_wait.parity.acquire.cta.shared::cta.b64 p, [%1], %2;\n\t"
        "selp.b32 %0, 1, 0, p;\n\t}"
        : "=r"(done) : "r"(mbar), "r"(parity) : "memory");
    while (!done) {
        asm volatile("{\n\t.reg .pred p;\n\t"
            "mbarrier.try_wait.parity.acquire.cta.shared::cta.b64 p, [%1], %2, 0x989680;\n\t"
            "selp.b32 %0, 1, 0, p;\n\t}"
            : "=r"(done) : "r"(mbar), "r"(parity) : "memory");
    }
}
#define CP_ASYNC16(dst, src) \
    asm volatile("cp.async.cg.shared.global [%0], [%1], 16;" :: "r"(dst), "l"(src))
#define CP_COMMIT() asm volatile("cp.async.commit_group;" ::: "memory")
#define CP_WAIT1()  asm volatile("cp.async.wait_group 1;" ::: "memory")

#define LDTM_X32(r, addr) \
    asm volatile( \
        "tcgen05.ld.sync.aligned.32x32b.x32.b32 " \
        "{%0, %1, %2, %3, %4, %5, %6, %7, " \
        " %8, %9, %10, %11, %12, %13, %14, %15, " \
        " %16, %17, %18, %19, %20, %21, %22, %23, " \
        " %24, %25, %26, %27, %28, %29, %30, %31}, [%32];" \
        : "=r"((r)[0]),  "=r"((r)[1]),  "=r"((r)[2]),  "=r"((r)[3]), \
          "=r"((r)[4]),  "=r"((r)[5]),  "=r"((r)[6]),  "=r"((r)[7]), \
          "=r"((r)[8]),  "=r"((r)[9]),  "=r"((r)[10]), "=r"((r)[11]), \
          "=r"((r)[12]), "=r"((r)[13]), "=r"((r)[14]), "=r"((r)[15]), \
          "=r"((r)[16]), "=r"((r)[17]), "=r"((r)[18]), "=r"((r)[19]), \
          "=r"((r)[20]), "=r"((r)[21]), "=r"((r)[22]), "=r"((r)[23]), \
          "=r"((r)[24]), "=r"((r)[25]), "=r"((r)[26]), "=r"((r)[27]), \
          "=r"((r)[28]), "=r"((r)[29]), "=r"((r)[30]), "=r"((r)[31]) \
        : "r"(addr))
#endif

// ---------------- routing kernels ----------------
__global__ void init_kernel() {
    int i = threadIdx.x;
    if (i < N_EXPERTS) g_cnt[i] = 0;
}

__global__ void gate_kernel(const float* __restrict__ x,
                            const float* __restrict__ Wg,
                            const float* __restrict__ bg,
                            float* __restrict__ gate_out)
{
    int warp = threadIdx.x >> 5;
    int lane = threadIdx.x & 31;
    int t = blockIdx.x * (blockDim.x >> 5) + warp;
    if (t >= T_TOKENS) return;

    float acc[N_EXPERTS];
#pragma unroll
    for (int e = 0; e < N_EXPERTS; e++) acc[e] = 0.0f;

    const float* xr = x + (size_t)t * D_MODEL;
    for (int d = lane; d < D_MODEL; d += 32) {
        float xv = xr[d];
        const float4 w0 = *(const float4*)(Wg + (size_t)d * N_EXPERTS);
        const float4 w1 = *(const float4*)(Wg + (size_t)d * N_EXPERTS + 4);
        acc[0] += xv * w0.x; acc[1] += xv * w0.y;
        acc[2] += xv * w0.z; acc[3] += xv * w0.w;
        acc[4] += xv * w1.x; acc[5] += xv * w1.y;
        acc[6] += xv * w1.z; acc[7] += xv * w1.w;
    }
#pragma unroll
    for (int e = 0; e < N_EXPERTS; e++) {
#pragma unroll
        for (int o = 16; o > 0; o >>= 1)
            acc[e] += __shfl_xor_sync(0xffffffffu, acc[e], o);
    }

    if (lane == 0) {
        float logit[N_EXPERTS];
        float mx = -1e30f;
#pragma unroll
        for (int e = 0; e < N_EXPERTS; e++) {
            logit[e] = acc[e] + bg[e];
            gate_out[(size_t)t * N_EXPERTS + e] = logit[e];
            mx = fmaxf(mx, logit[e]);
        }
        float p[N_EXPERTS];
        float sum = 0.0f;
#pragma unroll
        for (int e = 0; e < N_EXPERTS; e++) { p[e] = expf(logit[e] - mx); sum += p[e]; }
        float inv = 1.0f / sum;
#pragma unroll
        for (int e = 0; e < N_EXPERTS; e++) p[e] *= inv;

        int i0 = 0; float v0 = p[0];
#pragma unroll
        for (int e = 1; e < N_EXPERTS; e++) if (p[e] > v0) { v0 = p[e]; i0 = e; }
        int i1 = -1; float v1 = -1e30f;
#pragma unroll
        for (int e = 0; e < N_EXPERTS; e++) {
            if (e == i0) continue;
            if (p[e] > v1) { v1 = p[e]; i1 = e; }
        }
        g_topk_idx[t * 2 + 0] = i0; g_topk_w[t * 2 + 0] = v0;
        g_topk_idx[t * 2 + 1] = i1; g_topk_w[t * 2 + 1] = v1;
        atomicAdd(&g_cnt[i0], 1);
        atomicAdd(&g_cnt[i1], 1);
    }
}

__global__ void prefix_kernel() {
    if (threadIdx.x == 0) {
        int s = 0;
        for (int e = 0; e < N_EXPERTS; e++) {
            g_off[e] = s;
            g_cursor[e] = s;
            s += g_cnt[e];
        }
        g_off[N_EXPERTS] = s;
    }
}

__global__ void scatter_kernel() {
    int t = blockIdx.x * blockDim.x + threadIdx.x;
    if (t >= T_TOKENS) return;
#pragma unroll
    for (int k = 0; k < 2; k++) {
        int e = g_topk_idx[t * 2 + k];
        int pos = atomicAdd(&g_cursor[e], 1);
        g_slot_token[pos] = t;
        g_tok2slot[t * 2 + k] = pos;
    }
}

// gather + fp16-convert x rows into slot order
__global__ void gather_kernel(const float* __restrict__ x) {
    int idx = blockIdx.x * blockDim.x + threadIdx.x;
    int slot = idx >> 8;
    int c4 = idx & 255;
    int tok = g_slot_token[slot];
    float4 v = *(const float4*)(x + (size_t)tok * D_MODEL + c4 * 4);
    __half2 h0 = __floats2half2_rn(v.x, v.y);
    __half2 h1 = __floats2half2_rn(v.z, v.w);
    uint2 pk = make_uint2(*(uint32_t*)&h0, *(uint32_t*)&h1);
    *(uint2*)(g_A1 + (size_t)slot * D_MODEL + c4 * 4) = pk;
}

// transpose + fp16 convert: in [z][R][C] fp32 -> out [z][C][R] fp16
__global__ void transpose_kernel(const float* __restrict__ in, int R, int C, int which)
{
    __shared__ float tile[32][33];
    __half* out = which ? g_W2t : g_W1t;
    size_t base = (size_t)blockIdx.z * (size_t)R * C;
    int c0 = blockIdx.x * 32, r0 = blockIdx.y * 32;
    int tx = threadIdx.x & 31, ty = threadIdx.x >> 5;
#pragma unroll
    for (int i = 0; i < 32; i += 8)
        tile[ty + i][tx] = in[base + (size_t)(r0 + ty + i) * C + (c0 + tx)];
    __syncthreads();
#pragma unroll
    for (int q = 0; q < 2; q++) {
        int idx = threadIdx.x * 2 + q;
        int c = idx >> 4;
        int p = idx & 15;
        __half2 v = __floats2half2_rn(tile[2 * p][c], tile[2 * p + 1][c]);
        *(__half2*)(out + base + (size_t)(c0 + c) * R + (r0 + 2 * p)) = v;
    }
}

// ---------------- grouped GEMM (tcgen05 fp16, 256x256 tile, 3-stage ring) ----------------
// MODE 0: H[slot] = fp16(gelu(A1[slot] @ W1t^T + b1))   K=D_MODEL, N=D_FF
// MODE 1: Y[slot] = H[slot] @ W2t^T + b2  (fp32 out)    K=D_FF,    N=D_MODEL
template<int KDIM, int MODE>
__global__ void __launch_bounds__(256, 1) moe_gemm(const float* __restrict__ bias)
{
    extern __shared__ char smem[];
    const int tid = threadIdx.x;
    const int wid = tid >> 5, lane = tid & 31;

    const int e = blockIdx.z;
    const int mBase = g_off[e] + blockIdx.x * BM;
    const int mEnd  = g_off[e + 1];
    if (mBase >= mEnd) return;
    const int n0 = blockIdx.y * BN;

    const __half* Abase = (MODE == 0) ? g_A1 : g_H;
    const __half* Bt    = (MODE == 0) ? g_W1t : g_W2t;
    const int NB = (MODE == 0) ? D_FF : D_MODEL;
    const size_t eRowB = (size_t)e * NB;

#if USE_TCGEN05
    const uint32_t sb = smem_u32(smem);
    if (wid == 0) {
        asm volatile("tcgen05.alloc.cta_group::1.sync.aligned.shared::cta.b32 [%0], %1;"
                     :: "r"(sb + SM_TMEM), "r"(512u) : "memory");
        asm volatile("tcgen05.relinquish_alloc_permit.cta_group::1.sync.aligned;");
    }
    if (tid == 0) {
#pragma unroll
        for (int s = 0; s < NSTAGE; s++)
            asm volatile("mbarrier.init.shared.b64 [%0], 1;"
                         :: "r"(sb + SM_MBAR + s * 8) : "memory");
        asm volatile("mbarrier.init.shared.b64 [%0], 1;" :: "r"(sb + SM_DONE) : "memory");
    }
    __syncthreads();
    const uint32_t tmem = *(const uint32_t*)(smem + SM_TMEM);

    // cp.async mapping: 4 tiles (A0,A1,B0,B1), each 16KB = 1024 16B units.
    // 4096 units total / 256 threads = 16 units/thread.
    uint32_t dstU[16];
    const char* srcU[16];
#pragma unroll
    for (int j = 0; j < 16; j++) {
        int u = tid + j * 256;           // 0..4095
        int tile = u >> 10;              // 0=A0,1=A1,2=B0,3=B1
        int v = u & 1023;
        int row = v >> 3, c16 = v & 7;
        uint32_t off = (uint32_t)(row * 128 + c16 * 16);
        uint32_t so = off ^ ((off >> 3) & 0x70);
        dstU[j] = (uint32_t)tile * TILE16K + so;
        const __half* src;
        if (tile < 2)
            src = Abase + (size_t)(mBase + tile * 128 + row) * KDIM;
        else
            src = Bt + (eRowB + n0 + (tile - 2) * 128 + row) * (size_t)KDIM;
        srcU[j] = (const char*)src + c16 * 16;
    }

    constexpr int NT = KDIM / BK;

#pragma unroll
    for (int p = 0; p < NSTAGE - 1; p++) {
        uint32_t sbase = sb + SM_TILES + p * STAGE_B;
        size_t koff = (size_t)p * 128;   // BK halfs = 128 bytes
#pragma unroll
        for (int j = 0; j < 16; j++) CP_ASYNC16(sbase + dstU[j], srcU[j] + koff);
        CP_COMMIT();
    }

    for (int k = 0; k < NT; k++) {
        const int s = k % NSTAGE;                 // consume cursor
        CP_WAIT1();
        __syncthreads();

        if (wid == 0 && elect_one()) {
            asm volatile("fence.proxy.async.shared::cta;" ::: "memory");
            uint32_t st = sb + SM_TILES + s * STAGE_B;
            uint64_t a0 = make_desc_sw128(st);
            uint64_t a1 = make_desc_sw128(st + TILE16K);
            uint64_t b0 = make_desc_sw128(st + 2 * TILE16K);
            uint64_t b1 = make_desc_sw128(st + 3 * TILE16K);
#pragma unroll
            for (int sub = 0; sub < 4; sub++) {   // 4 x K=16 steps = BK 64
                uint32_t en = (k > 0 || sub > 0) ? 1u : 0u;
#define MMA_F16(dtm, ad, bd) \
                asm volatile( \
                    "{\n\t.reg .pred p;\n\tsetp.ne.u32 p, %4, 0;\n\t" \
                    "tcgen05.mma.cta_group::1.kind::f16 [%0], %1, %2, %3, " \
                    "{%5, %5, %5, %5}, p;\n\t}" \
                    :: "r"(dtm), "l"(ad), "l"(bd), "r"(IDESC_F16), "r"(en), "r"(0u) \
                    : "memory")
                MMA_F16(tmem +   0, a0 + sub * 2, b0 + sub * 2);
                MMA_F16(tmem + 128, a0 + sub * 2, b1 + sub * 2);
                MMA_F16(tmem + 256, a1 + sub * 2, b0 + sub * 2);
                MMA_F16(tmem + 384, a1 + sub * 2, b1 + sub * 2);
#undef MMA_F16
            }
            asm volatile(
                "tcgen05.commit.cta_group::1.mbarrier::arrive::one.shared::cluster.b64 [%0];"
                :: "r"(sb + SM_MBAR + s * 8) : "memory");
        }

        const int pend = k + NSTAGE - 1;          // K-tile to prefetch now
        if (pend < NT) {
            const int ps = pend % NSTAGE;
            if (pend >= NSTAGE) {
                // wait for the MMA that consumed this stage at k-tile (pend - NSTAGE):
                // that was the (pend/NSTAGE - 1)-th commit to mbar[ps] -> its parity.
                uint32_t pr = ((uint32_t)(pend / NSTAGE) - 1u) & 1u;
                mbar_wait(sb + SM_MBAR + ps * 8, pr);
            }
            uint32_t sbase = sb + SM_TILES + ps * STAGE_B;
            size_t koff = (size_t)pend * 128;
#pragma unroll
            for (int j = 0; j < 16; j++) CP_ASYNC16(sbase + dstU[j], srcU[j] + koff);
        }
        CP_COMMIT();
    }

    if (wid == 0 && elect_one()) {
        asm volatile(
            "tcgen05.commit.cta_group::1.mbarrier::arrive::one.shared::cluster.b64 [%0];"
            :: "r"(sb + SM_DONE) : "memory");
    }
    mbar_wait(sb + SM_DONE, 0);
    asm volatile("tcgen05.fence::after_thread_sync;" ::: "memory");

    // epilogue: warps 0-3 -> m-half 0 (acc @0,@128), warps 4-7 -> m-half 1 (@256,@384)
    {
        const int mh = wid >> 2;
        const int row = (wid & 3) * 32 + lane;
        const int slot = mBase + mh * 128 + row;
        const bool valid = slot < mEnd;
#pragma unroll
        for (int nh = 0; nh < 2; nh++) {
            const float* bb = bias + (size_t)e * NB + n0 + nh * 128;
            const uint32_t tm = tmem + mh * 256 + nh * 128;
            __half* dstH = 0; float* dstY = 0;
            if (valid) {
                if (MODE == 0) dstH = g_H + (size_t)slot * D_FF + n0 + nh * 128;
                else           dstY = g_Y + (size_t)slot * D_MODEL + n0 + nh * 128;
            }
#pragma unroll
            for (int nb = 0; nb < 4; nb++) {
                uint32_t dr[32];
                LDTM_X32(dr, tm + nb * 32);
                asm volatile("tcgen05.wait::ld.sync.aligned;" ::: "memory");
                if (valid) {
#pragma unroll
                    for (int q = 0; q < 8; q++) {
                        float v0 = __uint_as_float(dr[q * 4 + 0]) + bb[nb * 32 + q * 4 + 0];
                        float v1 = __uint_as_float(dr[q * 4 + 1]) + bb[nb * 32 + q * 4 + 1];
                        float v2 = __uint_as_float(dr[q * 4 + 2]) + bb[nb * 32 + q * 4 + 2];
                        float v3 = __uint_as_float(dr[q * 4 + 3]) + bb[nb * 32 + q * 4 + 3];
                        if (MODE == 0) {
                            __half2 h0 = __floats2half2_rn(gelu_exact(v0), gelu_exact(v1));
                            __half2 h1 = __floats2half2_rn(gelu_exact(v2), gelu_exact(v3));
                            uint2 pk = make_uint2(*(uint32_t*)&h0, *(uint32_t*)&h1);
                            *(uint2*)(dstH + nb * 32 + q * 4) = pk;
                        } else {
                            float4 o; o.x = v0; o.y = v1; o.z = v2; o.w = v3;
                            *(float4*)(dstY + nb * 32 + q * 4) = o;
                        }
                    }
                }
            }
        }
    }
    __syncthreads();
    if (wid == 0) {
        asm volatile("tcgen05.dealloc.cta_group::1.sync.aligned.b32 %0, %1;"
                     :: "r"(tmem), "r"(512u));
    }
#else
    // ---------- SIMT fallback (non-'a' PTX pass only; runtime uses the 'a' cubin) ----------
    __syncthreads();
    float (*As)[132] = (float(*)[132])(smem + SM_TILES);
    float (*Bs)[132] = (float(*)[132])(smem + SM_TILES + 16 * 132 * 4);
    const int ty = tid >> 4, tx = tid & 15;
    const int lr = tid >> 1;
    const int lc = (tid & 1) * 8;

    for (int mh = 0; mh < 2; mh++) {
        const __half* arow = Abase + (size_t)(mBase + mh * 128 + lr) * KDIM;
        for (int nh = 0; nh < 2; nh++) {
            const int nhh = n0 + nh * 128;
            const __half* brow = Bt + (eRowB + nhh + lr) * (size_t)KDIM + lc;
            float acc[8][8];
#pragma unroll
            for (int i = 0; i < 8; i++)
#pragma unroll
                for (int j = 0; j < 8; j++) acc[i][j] = 0.0f;

            for (int k0 = 0; k0 < KDIM; k0 += 16) {
#pragma unroll
                for (int q = 0; q < 8; q++) {
                    As[lc + q][lr] = __half2float(arow[k0 + lc + q]);
                    Bs[lc + q][lr] = __half2float(brow[k0 + q]);
                }
                __syncthreads();
#pragma unroll
                for (int kk = 0; kk < 16; kk++) {
                    float a[8], bfr[8];
#pragma unroll
                    for (int i = 0; i < 8; i++) a[i] = As[kk][ty * 8 + i];
#pragma unroll
                    for (int j = 0; j < 8; j++) bfr[j] = Bs[kk][tx * 8 + j];
#pragma unroll
                    for (int i = 0; i < 8; i++)
#pragma unroll
                        for (int j = 0; j < 8; j++) acc[i][j] += a[i] * bfr[j];
                }
                __syncthreads();
            }
            const float* bb = bias + (size_t)e * NB + nhh;
#pragma unroll
            for (int i = 0; i < 8; i++) {
                int slot = mBase + mh * 128 + ty * 8 + i;
                if (slot >= mEnd) continue;
#pragma unroll
                for (int j = 0; j < 8; j++) {
                    float v = acc[i][j] + bb[tx * 8 + j];
                    if (MODE == 0)
                        g_H[(size_t)slot * D_FF + nhh + tx * 8 + j] = __float2half_rn(gelu_exact(v));
                    else
                        g_Y[(size_t)slot * D_MODEL + nhh + tx * 8 + j] = v;
                }
            }
            __syncthreads();
        }
    }
#endif
}

// ---------------- combine ----------------
__global__ void combine_kernel(float* __restrict__ out) {
    int idx = blockIdx.x * blockDim.x + threadIdx.x;
    int t  = idx >> 8;
    int d4 = idx & 255;
    int s0 = g_tok2slot[t * 2 + 0], s1 = g_tok2slot[t * 2 + 1];
    float w0 = g_topk_w[t * 2 + 0], w1 = g_topk_w[t * 2 + 1];
    float4 a = *(const float4*)(g_Y + (size_t)s0 * D_MODEL + d4 * 4);
    float4 b = *(const float4*)(g_Y + (size_t)s1 * D_MODEL + d4 * 4);
    float4 o;
    o.x = w0 * a.x + w1 * b.x;
    o.y = w0 * a.y + w1 * b.y;
    o.z = w0 * a.z + w1 * b.z;
    o.w = w0 * a.w + w1 * b.w;
    *(float4*)(out + (size_t)t * D_MODEL + d4 * 4) = o;
}

// ---------------- host launch ----------------
extern "C" void kernel_launch(void* const* d_in, const int* in_sizes, int n_in,
                              void* d_out, int out_size)
{
    const float* x  = (const float*)d_in[0];
    const float* Wg = (const float*)d_in[1];
    const float* bg = (const float*)d_in[2];
    const float* W1 = (const float*)d_in[3];
    const float* b1 = (const float*)d_in[4];
    const float* W2 = (const float*)d_in[5];
    const float* b2 = (const float*)d_in[6];
    float* out = (float*)d_out;

    cudaFuncSetAttribute(moe_gemm<D_MODEL, 0>,
                         cudaFuncAttributeMaxDynamicSharedMemorySize, SMEM_TOTAL);
    cudaFuncSetAttribute(moe_gemm<D_FF, 1>,
                         cudaFuncAttributeMaxDynamicSharedMemorySize, SMEM_TOTAL);

    transpose_kernel<<<dim3(D_FF / 32, D_MODEL / 32, N_EXPERTS), 256>>>(W1, D_MODEL, D_FF, 0);
    transpose_kernel<<<dim3(D_MODEL / 32, D_FF / 32, N_EXPERTS), 256>>>(W2, D_FF, D_MODEL, 1);

    init_kernel<<<1, 32>>>();
    gate_kernel<<<T_TOKENS / 8, 256>>>(x, Wg, bg, out + (size_t)T_TOKENS * D_MODEL);
    prefix_kernel<<<1, 32>>>();
    scatter_kernel<<<T_TOKENS / 256, 256>>>();
    gather_kernel<<<(TOTAL_SLOTS * 256) / 256, 256>>>(x);

    dim3 g1(TOTAL_SLOTS / BM, D_FF / BN, N_EXPERTS);      // 64 x 16 x 8 (early-exit x)
    moe_gemm<D_MODEL, 0><<<g1, 256, SMEM_TOTAL>>>(b1);

    dim3 g2(TOTAL_SLOTS / BM, D_MODEL / BN, N_EXPERTS);   // 64 x 4 x 8
    moe_gemm<D_FF, 1><<<g2, 256, SMEM_TOTAL>>>(b2);

    combine_kernel<<<(T_TOKENS * 256) / 256, 256>>>(out);
}